// round 12
// baseline (speedup 1.0000x reference)
#include <cuda_runtime.h>
#include <cuda_bf16.h>
#include <cstdint>

// ---------------------------------------------------------------------------
// RNN: h_t = tanh(X_t @ W_xh + b_h + h_{t-1} @ W_hh) ; y_t = h_t @ W_hq + b_q
// out = [outputs (T*B*O floats) | states (T*B*H floats)]
// T=512 B=64 H=1024 I=512 O=512
//
// R12: recurrence tensorized with the SAME proven mma.sync bf16 2-split
// machinery as the GEMMs. 64 CTAs x 256 thr; W_hh slice resident in smem;
// h streamed as pre-split bf16 from global scratch via double-buffered smem
// chunks; 64-CTA release/acquire barrier per step.
// ---------------------------------------------------------------------------

#define RT 512
#define RB 64
#define RH 1024
#define RI 512
#define RO 512

__device__ unsigned g_bar2[2];
// pre-split hidden state scratch: [pingpong][split][m*1024 + k] bf16
__device__ __align__(16) __nv_bfloat16 g_hB[2][2][RB * RH];
// split+transposed weights: Wt[n][k] bf16
__device__ __align__(16) __nv_bfloat16 g_Wxh1t[RH * RI];
__device__ __align__(16) __nv_bfloat16 g_Wxh2t[RH * RI];
__device__ __align__(16) __nv_bfloat16 g_Whq1t[RO * RH];
__device__ __align__(16) __nv_bfloat16 g_Whq2t[RO * RH];
__device__ __align__(16) __nv_bfloat16 g_Whh1t[RH * RH];
__device__ __align__(16) __nv_bfloat16 g_Whh2t[RH * RH];

// ---- helpers ----
__device__ __forceinline__ void red_release_add(unsigned* p, unsigned v) {
    asm volatile("red.release.gpu.global.add.u32 [%0], %1;" :: "l"(p), "r"(v)
                 : "memory");
}
__device__ __forceinline__ unsigned ld_acquire(const unsigned* p) {
    unsigned v;
    asm volatile("ld.acquire.gpu.global.u32 %0, [%1];" : "=r"(v) : "l"(p)
                 : "memory");
    return v;
}
__device__ __forceinline__ uint32_t smem_u32(const void* p) {
    uint32_t a;
    asm("{ .reg .u64 t; cvta.to.shared.u64 t, %1; cvt.u32.u64 %0, t; }"
        : "=r"(a) : "l"(p));
    return a;
}
__device__ __forceinline__ uint32_t cvt2bf(float lo, float hi) {
    uint32_t r;
    asm("cvt.rn.bf16x2.f32 %0, %1, %2;" : "=r"(r) : "f"(hi), "f"(lo));
    return r;
}
__device__ __forceinline__ void ldm4(uint32_t* r, uint32_t addr) {
    asm volatile(
        "ldmatrix.sync.aligned.m8n8.x4.shared.b16 {%0,%1,%2,%3}, [%4];"
        : "=r"(r[0]), "=r"(r[1]), "=r"(r[2]), "=r"(r[3]) : "r"(addr));
}
__device__ __forceinline__ void mma_bf16(float* c, const uint32_t* a,
                                         uint32_t b0, uint32_t b1) {
    asm volatile(
        "mma.sync.aligned.m16n8k16.row.col.f32.bf16.bf16.f32 "
        "{%0,%1,%2,%3}, {%4,%5,%6,%7}, {%8,%9}, {%0,%1,%2,%3};"
        : "+f"(c[0]), "+f"(c[1]), "+f"(c[2]), "+f"(c[3])
        : "r"(a[0]), "r"(a[1]), "r"(a[2]), "r"(a[3]), "r"(b0), "r"(b1));
}
__device__ __forceinline__ uint4 ldcg128(const void* p) {
    uint4 v;
    asm volatile("ld.global.cg.v4.u32 {%0,%1,%2,%3}, [%4];"
                 : "=r"(v.x), "=r"(v.y), "=r"(v.z), "=r"(v.w) : "l"(p));
    return v;
}
__device__ __forceinline__ void stcg32u(void* p, uint32_t v) {
    asm volatile("st.global.cg.u32 [%0], %1;" :: "l"(p), "r"(v));
}

// ---------------------------------------------------------------------------
// wsplit: W[K,N] fp32 -> Wt1/Wt2[N,K] bf16 (transpose + 2-term split).
// ---------------------------------------------------------------------------
__global__ __launch_bounds__(256) void wsplit(
    const float* __restrict__ W, __nv_bfloat16* __restrict__ Wt1,
    __nv_bfloat16* __restrict__ Wt2, int K, int N, int reset)
{
    __shared__ float tile[32][33];
    const int tx = threadIdx.x & 31, ty = threadIdx.x >> 5;
    const int bx = blockIdx.x, by = blockIdx.y;
    if (reset && bx == 0 && by == 0 && threadIdx.x == 0) {
        g_bar2[0] = 0u;
        g_bar2[1] = 0u;
    }
    const int n = bx * 32 + tx;
#pragma unroll
    for (int i = 0; i < 4; i++) {
        int k = by * 32 + ty + i * 8;
        tile[ty + i * 8][tx] = W[(size_t)k * N + n];
    }
    __syncthreads();
    const int k2 = by * 32 + tx;
#pragma unroll
    for (int i = 0; i < 4; i++) {
        int n2 = bx * 32 + ty + i * 8;
        float v = tile[tx][ty + i * 8];
        __nv_bfloat16 b1 = __float2bfloat16_rn(v);
        float r = v - __bfloat162float(b1);
        Wt1[(size_t)n2 * K + k2] = b1;
        Wt2[(size_t)n2 * K + k2] = __float2bfloat16_rn(r);
    }
}

// ---------------------------------------------------------------------------
// mma_gemm (unchanged, proven R11): C = A(fp32) @ Wt + bias
// ---------------------------------------------------------------------------
#define AS1 0
#define AS2 18432
#define BS1 36864
#define BS2 46080
#define BIAS_OFF 55296
#define MM_SMEM 55552
#define RSTR 144

__global__ __launch_bounds__(256) void mma_gemm(
    const float* __restrict__ A,
    const __nv_bfloat16* __restrict__ Bt1,
    const __nv_bfloat16* __restrict__ Bt2,
    const float* __restrict__ bias, float* __restrict__ C,
    int M, int N, int K)
{
    extern __shared__ __align__(16) char ts[];
    const uint32_t sb = smem_u32(ts);
    float* sBias = (float*)(ts + BIAS_OFF);

    const int tid = threadIdx.x;
    const int wid = tid >> 5;
    const int lane = tid & 31;
    const int n0 = blockIdx.x * 64;
    const int m0 = blockIdx.y * 128;

    const int mw = (wid & 3) * 32;
    const int nw = (wid >> 2) * 32;
    const int l16 = lane & 15;
    const int lhi = lane >> 4;

    if (tid < 64) sBias[tid] = bias[n0 + tid];

    float acc[2][4][4];
#pragma unroll
    for (int i = 0; i < 2; i++)
#pragma unroll
        for (int j = 0; j < 4; j++)
#pragma unroll
            for (int q = 0; q < 4; q++) acc[i][j][q] = 0.0f;

    const int sr = tid >> 4;
    const int sc = tid & 15;
    const int br = tid >> 3;
    const int bc = tid & 7;

    const int nch = K >> 6;
    for (int c = 0; c < nch; ++c) {
        const int k0 = c << 6;
        if (c > 0) __syncthreads();

#pragma unroll
        for (int it = 0; it < 8; it++) {
            int r = sr + it * 16;
            float4 v = *(const float4*)(A + (size_t)(m0 + r) * K + k0 + sc * 4);
            uint32_t p1a = cvt2bf(v.x, v.y);
            uint32_t p1b = cvt2bf(v.z, v.w);
            float fx = v.x - __uint_as_float(p1a << 16);
            float fy = v.y - __uint_as_float(p1a & 0xFFFF0000u);
            float fz = v.z - __uint_as_float(p1b << 16);
            float fw = v.w - __uint_as_float(p1b & 0xFFFF0000u);
            uint32_t p2a = cvt2bf(fx, fy);
            uint32_t p2b = cvt2bf(fz, fw);
            uint32_t off = (uint32_t)(r * RSTR + sc * 8);
            *(unsigned long long*)(ts + AS1 + off) =
                (unsigned long long)p1a | ((unsigned long long)p1b << 32);
            *(unsigned long long*)(ts + AS2 + off) =
                (unsigned long long)p2a | ((unsigned long long)p2b << 32);
        }
#pragma unroll
        for (int it = 0; it < 2; it++) {
            int r = br + it * 32;
            size_t go = (size_t)(n0 + r) * K + k0 + bc * 8;
            uint4 v1 = *(const uint4*)(Bt1 + go);
            uint4 v2 = *(const uint4*)(Bt2 + go);
            uint32_t off = (uint32_t)(r * RSTR + bc * 16);
            *(uint4*)(ts + BS1 + off) = v1;
            *(uint4*)(ts + BS2 + off) = v2;
        }
        __syncthreads();

#pragma unroll
        for (int ks = 0; ks < 4; ks++) {
            const uint32_t kb = (uint32_t)((ks * 16 + lhi * 8) * 2);

            uint32_t a1[2][4], a2[2][4];
#pragma unroll
            for (int mf = 0; mf < 2; mf++) {
                uint32_t ao = (uint32_t)((mw + mf * 16 + l16) * RSTR) + kb;
                ldm4(a1[mf], sb + AS1 + ao);
                ldm4(a2[mf], sb + AS2 + ao);
            }
            uint32_t b1[2][4], b2[2][4];
#pragma unroll
            for (int np = 0; np < 2; np++) {
                uint32_t bo = (uint32_t)((nw + np * 16 + l16) * RSTR) + kb;
                ldm4(b1[np], sb + BS1 + bo);
                ldm4(b2[np], sb + BS2 + bo);
            }
#pragma unroll
            for (int mf = 0; mf < 2; mf++)
#pragma unroll
                for (int np = 0; np < 2; np++)
#pragma unroll
                    for (int hf = 0; hf < 2; hf++) {
                        float* cc = acc[mf][np * 2 + hf];
                        mma_bf16(cc, a1[mf], b1[np][hf], b1[np][hf + 2]);
                        mma_bf16(cc, a1[mf], b2[np][hf], b2[np][hf + 2]);
                        mma_bf16(cc, a2[mf], b1[np][hf], b1[np][hf + 2]);
                    }
        }
    }
    __syncthreads();

    const int g = lane >> 2;
    const int t = lane & 3;
#pragma unroll
    for (int mf = 0; mf < 2; mf++) {
#pragma unroll
        for (int nf = 0; nf < 4; nf++) {
            const int col = nw + nf * 8 + 2 * t;
            const float bx0 = sBias[col];
            const float bx1 = sBias[col + 1];
            const int row = m0 + mw + mf * 16 + g;
            float* cp = C + (size_t)row * N + n0 + col;
            float2 o0 = make_float2(acc[mf][nf][0] + bx0, acc[mf][nf][1] + bx1);
            float2 o1 = make_float2(acc[mf][nf][2] + bx0, acc[mf][nf][3] + bx1);
            *(float2*)cp = o0;
            *(float2*)(cp + (size_t)8 * N) = o1;
        }
    }
}

// ---------------------------------------------------------------------------
// 64-CTA grid barrier (release/acquire, proven R8 semantics)
// ---------------------------------------------------------------------------
__device__ __forceinline__ void grid_bar64(unsigned* epoch, int tid) {
    __syncthreads();
    *epoch += 1;
    if (tid == 0) {
        red_release_add(&g_bar2[0], 1u);
        const unsigned tgt = (*epoch) * 64u;
        while (ld_acquire(&g_bar2[0]) < tgt) {}
    }
    __syncthreads();
}

// ---------------------------------------------------------------------------
// rnn_rec_tc: tensorized recurrence. 64 CTAs x 256 thr (8 warps).
// CTA cols n0 = cid*16. Warp wid = mq + 4*kh: m16-tile mq, k-half kh.
// Smem: W slices [16n][1024k] x2 splits (2064B rows), h chunk double-buffer
// [64m][64k] x2 splits (144B rows), RED 4KB.
// ---------------------------------------------------------------------------
#define WS1R 0
#define WS2R 33024
#define HSR 66048
#define HBUFSZ 18432        // one buffer: 2 splits x 64 x 144
#define REDR 102912
#define REC_SMEM 107008

__global__ __launch_bounds__(256) void rnn_rec_tc(
    const __nv_bfloat16* __restrict__ Whh1,
    const __nv_bfloat16* __restrict__ Whh2,
    float* __restrict__ states)
{
    extern __shared__ __align__(16) char rs[];
    const uint32_t sb = smem_u32(rs);
    float* RED = (float*)(rs + REDR);

    const int tid = threadIdx.x;
    const int wid = tid >> 5;
    const int lane = tid & 31;
    const int l16 = lane & 15;
    const int lhi = lane >> 4;
    const int mq = wid & 3;       // m16 tile
    const int kh = wid >> 2;      // k half
    const int n0 = blockIdx.x * 16;

    // one-time: W_hh slice [16n][1024k] both splits into smem
    for (int idx = tid; idx < 16 * 128; idx += 256) {
        int r = idx >> 7, c = idx & 127;
        *(uint4*)(rs + WS1R + r * 2064 + c * 16) =
            *(const uint4*)(Whh1 + (size_t)(n0 + r) * RH + c * 8);
        *(uint4*)(rs + WS2R + r * 2064 + c * 16) =
            *(const uint4*)(Whh2 + (size_t)(n0 + r) * RH + c * 8);
    }
    __syncthreads();

    unsigned epoch = 0;

    // t = 0: h_0 = tanh(xp); write states + split scratch
    {
        int m = tid >> 2, j4 = (tid & 3) * 4;
        float* op = states + (size_t)m * RH + n0 + j4;
        float4 xp = *(float4*)op;
        float4 hv;
        hv.x = tanhf(xp.x); hv.y = tanhf(xp.y);
        hv.z = tanhf(xp.z); hv.w = tanhf(xp.w);
        *(float4*)op = hv;
        size_t ho = (size_t)m * RH + n0 + j4;
        uint32_t q1a = cvt2bf(hv.x, hv.y);
        uint32_t q1b = cvt2bf(hv.z, hv.w);
        float rx = hv.x - __uint_as_float(q1a << 16);
        float ry = hv.y - __uint_as_float(q1a & 0xFFFF0000u);
        float rz = hv.z - __uint_as_float(q1b << 16);
        float rw = hv.w - __uint_as_float(q1b & 0xFFFF0000u);
        stcg32u(&g_hB[0][0][ho], q1a);
        stcg32u(&g_hB[0][0][ho + 2], q1b);
        stcg32u(&g_hB[0][1][ho], cvt2bf(rx, ry));
        stcg32u(&g_hB[0][1][ho + 2], cvt2bf(rz, rw));
    }
    grid_bar64(&epoch, tid);

    const int sr0 = tid >> 3;     // staging row base (0..31)
    const int sc8 = tid & 7;      // staging 16B col

    for (int t = 1; t < RT; ++t) {
        const __nv_bfloat16* h1 = g_hB[(t - 1) & 1][0];
        const __nv_bfloat16* h2 = g_hB[(t - 1) & 1][1];

        // prefetch chunk 0
        uint4 p1[2], p2[2];
#pragma unroll
        for (int i = 0; i < 2; i++) {
            size_t off = (size_t)(sr0 + i * 32) * RH + sc8 * 8;
            p1[i] = ldcg128(h1 + off);
            p2[i] = ldcg128(h2 + off);
        }

        float acc[2][2][4];
#pragma unroll
        for (int x = 0; x < 2; x++)
#pragma unroll
            for (int y = 0; y < 2; y++)
#pragma unroll
                for (int q = 0; q < 4; q++) acc[x][y][q] = 0.0f;

        for (int c = 0; c < 16; ++c) {
            const uint32_t buf = HSR + (uint32_t)(c & 1) * HBUFSZ;
            // commit staged chunk
#pragma unroll
            for (int i = 0; i < 2; i++) {
                uint32_t so = buf + (uint32_t)(sr0 + i * 32) * 144 + sc8 * 16;
                *(uint4*)(rs + so) = p1[i];
                *(uint4*)(rs + so + 9216) = p2[i];
            }
            __syncthreads();
            // prefetch next chunk
            if (c < 15) {
#pragma unroll
                for (int i = 0; i < 2; i++) {
                    size_t off = (size_t)(sr0 + i * 32) * RH + (c + 1) * 64 + sc8 * 8;
                    p1[i] = ldcg128(h1 + off);
                    p2[i] = ldcg128(h2 + off);
                }
            }
            // compute: 2 k16 steps for this warp's k-half
#pragma unroll
            for (int ks2 = 0; ks2 < 2; ks2++) {
                const int ks = kh * 2 + ks2;
                uint32_t a1[4], a2[4], b1[4], b2[4];
                uint32_t ao = buf + (uint32_t)((mq * 16 + l16) * 144 +
                                               (ks * 16 + lhi * 8) * 2);
                ldm4(a1, sb + ao);
                ldm4(a2, sb + ao + 9216);
                uint32_t bo = WS1R + (uint32_t)(l16 * 2064 +
                                                (c * 64 + ks * 16 + lhi * 8) * 2);
                ldm4(b1, sb + bo);
                ldm4(b2, sb + bo + (WS2R - WS1R));
#pragma unroll
                for (int tile = 0; tile < 2; tile++) {
                    float* cc = acc[ks2][tile];
                    mma_bf16(cc, a1, b1[tile], b1[tile + 2]);
                    mma_bf16(cc, a1, b2[tile], b2[tile + 2]);
                    mma_bf16(cc, a2, b1[tile], b1[tile + 2]);
                }
            }
        }

        // merge ks2 chains
        float fin[2][4];
#pragma unroll
        for (int tile = 0; tile < 2; tile++)
#pragma unroll
            for (int q = 0; q < 4; q++)
                fin[tile][q] = acc[0][tile][q] + acc[1][tile][q];

        // cross k-half reduce
        if (kh == 1) {
            float* rp = RED + (size_t)(mq * 32 + lane) * 8;
            *(float4*)rp = *(float4*)fin[0];
            *(float4*)(rp + 4) = *(float4*)fin[1];
        }
        __syncthreads();

        if (kh == 0) {
            const float* rp = RED + (size_t)(mq * 32 + lane) * 8;
            float4 r0 = *(const float4*)rp;
            float4 r1 = *(const float4*)(rp + 4);
            fin[0][0] += r0.x; fin[0][1] += r0.y; fin[0][2] += r0.z; fin[0][3] += r0.w;
            fin[1][0] += r1.x; fin[1][1] += r1.y; fin[1][2] += r1.z; fin[1][3] += r1.w;

            const int g = lane >> 2;
            const int tq = lane & 3;
            float* st_t = states + (size_t)t * (RB * RH);
            const int pp = t & 1;
#pragma unroll
            for (int tile = 0; tile < 2; tile++) {
                const int col = n0 + tile * 8 + 2 * tq;
#pragma unroll
                for (int rh = 0; rh < 2; rh++) {
                    const int row = mq * 16 + g + rh * 8;
                    float* op = st_t + (size_t)row * RH + col;
                    float2 xp = *(float2*)op;
                    float v0 = tanhf(xp.x + fin[tile][rh * 2 + 0]);
                    float v1 = tanhf(xp.y + fin[tile][rh * 2 + 1]);
                    *(float2*)op = make_float2(v0, v1);
                    uint32_t q1 = cvt2bf(v0, v1);
                    float e0 = v0 - __uint_as_float(q1 << 16);
                    float e1 = v1 - __uint_as_float(q1 & 0xFFFF0000u);
                    size_t ho = (size_t)row * RH + col;
                    stcg32u(&g_hB[pp][0][ho], q1);
                    stcg32u(&g_hB[pp][1][ho], cvt2bf(e0, e1));
                }
            }
        }

        if (t < RT - 1) grid_bar64(&epoch, tid);
    }
}

// ---------------------------------------------------------------------------
extern "C" void kernel_launch(void* const* d_in, const int* in_sizes, int n_in,
                              void* d_out, int out_size)
{
    const float* X    = (const float*)d_in[0];
    const float* W_xh = (const float*)d_in[1];
    const float* W_hh = (const float*)d_in[2];
    const float* b_h  = (const float*)d_in[3];
    const float* W_hq = (const float*)d_in[4];
    const float* b_q  = (const float*)d_in[5];

    float* outputs = (float*)d_out;                      // [T*B, O]
    float* states  = outputs + (size_t)RT * RB * RO;     // [T*B, H]

    const int M = RT * RB;  // 32768

    __nv_bfloat16 *pWxh1, *pWxh2, *pWhq1, *pWhq2, *pWhh1, *pWhh2;
    cudaGetSymbolAddress((void**)&pWxh1, g_Wxh1t);
    cudaGetSymbolAddress((void**)&pWxh2, g_Wxh2t);
    cudaGetSymbolAddress((void**)&pWhq1, g_Whq1t);
    cudaGetSymbolAddress((void**)&pWhq2, g_Whq2t);
    cudaGetSymbolAddress((void**)&pWhh1, g_Whh1t);
    cudaGetSymbolAddress((void**)&pWhh2, g_Whh2t);

    cudaFuncSetAttribute(mma_gemm,
                         cudaFuncAttributeMaxDynamicSharedMemorySize, MM_SMEM);
    cudaFuncSetAttribute(rnn_rec_tc,
                         cudaFuncAttributeMaxDynamicSharedMemorySize, REC_SMEM);

    // weight transforms (first one resets barrier counters)
    wsplit<<<dim3(RH / 32, RI / 32), 256>>>(W_xh, pWxh1, pWxh2, RI, RH, 1);
    wsplit<<<dim3(RO / 32, RH / 32), 256>>>(W_hq, pWhq1, pWhq2, RH, RO, 0);
    wsplit<<<dim3(RH / 32, RH / 32), 256>>>(W_hh, pWhh1, pWhh2, RH, RH, 0);

    // Xproj: states <- X @ W_xh + b_h
    mma_gemm<<<dim3(RH / 64, M / 128), 256, MM_SMEM>>>(
        X, pWxh1, pWxh2, b_h, states, M, RH, RI);

    // tensorized recurrence
    rnn_rec_tc<<<64, 256, REC_SMEM>>>(pWhh1, pWhh2, states);

    // outputs <- states @ W_hq + b_q
    mma_gemm<<<dim3(RO / 64, M / 128), 256, MM_SMEM>>>(
        states, pWhq1, pWhq2, b_q, outputs, M, RO, RH);
}

// round 13
// speedup vs baseline: 1.3843x; 1.3843x over previous
#include <cuda_runtime.h>
#include <cuda_bf16.h>
#include <cstdint>

// ---------------------------------------------------------------------------
// RNN: h_t = tanh(X_t @ W_xh + b_h + h_{t-1} @ W_hh) ; y_t = h_t @ W_hq + b_q
// out = [outputs (T*B*O floats) | states (T*B*H floats)]
// T=512 B=64 H=1024 I=512 O=512
//
// R13: revert to R11 (mma.sync bf16 2-split GEMMs + scalar f32x2 recurrence).
// One change: hierarchical grid barrier (8 sub-counters x 8 CTAs -> root)
// to cut the 64-way same-address L2 atomic serialization (~1750 -> ~450 cyc).
// ---------------------------------------------------------------------------

#define RT 512
#define RB 64
#define RH 1024
#define RI 512
#define RO 512

// hierarchical barrier state: [group][sub] counters + [group] root,
// each on its own 128B line.
__device__ unsigned g_barSub[2][8][32];
__device__ unsigned g_barRoot[2][32];

__device__ __align__(16) float2 g_hT[2][RH][RB / 2];
// split+transposed weights: Wt[n][k] bf16
__device__ __align__(16) __nv_bfloat16 g_Wxh1t[RH * RI];
__device__ __align__(16) __nv_bfloat16 g_Wxh2t[RH * RI];
__device__ __align__(16) __nv_bfloat16 g_Whq1t[RO * RH];
__device__ __align__(16) __nv_bfloat16 g_Whq2t[RO * RH];

// ---- scalar f32x2 helpers (recurrence) ----
__device__ __forceinline__ unsigned long long ffma2(unsigned long long a,
                                                    unsigned long long b,
                                                    unsigned long long c) {
    unsigned long long d;
    asm("fma.rn.f32x2 %0, %1, %2, %3;" : "=l"(d) : "l"(a), "l"(b), "l"(c));
    return d;
}
__device__ __forceinline__ unsigned long long add2(unsigned long long a,
                                                   unsigned long long b) {
    unsigned long long d;
    asm("add.rn.f32x2 %0, %1, %2;" : "=l"(d) : "l"(a), "l"(b));
    return d;
}
__device__ __forceinline__ unsigned long long pack2(float lo, float hi) {
    unsigned long long r;
    asm("mov.b64 %0, {%1, %2};" : "=l"(r) : "f"(lo), "f"(hi));
    return r;
}
__device__ __forceinline__ float2 unpack2(unsigned long long v) {
    float lo, hi;
    asm("mov.b64 {%0, %1}, %2;" : "=f"(lo), "=f"(hi) : "l"(v));
    return make_float2(lo, hi);
}
__device__ __forceinline__ unsigned long long ldcg64(const void* p) {
    unsigned long long v;
    asm volatile("ld.global.cg.b64 %0, [%1];" : "=l"(v) : "l"(p));
    return v;
}
__device__ __forceinline__ void stcg32(float* p, float v) {
    asm volatile("st.global.cg.f32 [%0], %1;" :: "l"(p), "f"(v));
}
__device__ __forceinline__ void stcg64(void* p, unsigned long long v) {
    asm volatile("st.global.cg.b64 [%0], %1;" :: "l"(p), "l"(v));
}
__device__ __forceinline__ unsigned atom_acqrel_add(unsigned* p, unsigned v) {
    unsigned old;
    asm volatile("atom.add.acq_rel.gpu.global.u32 %0, [%1], %2;"
                 : "=r"(old) : "l"(p), "r"(v) : "memory");
    return old;
}
__device__ __forceinline__ void red_release_add(unsigned* p, unsigned v) {
    asm volatile("red.release.gpu.global.add.u32 [%0], %1;" :: "l"(p), "r"(v)
                 : "memory");
}
__device__ __forceinline__ unsigned ld_acquire(const unsigned* p) {
    unsigned v;
    asm volatile("ld.acquire.gpu.global.u32 %0, [%1];" : "=r"(v) : "l"(p)
                 : "memory");
    return v;
}

// ---- tensor-core helpers (baseline PTX: sm_80+, valid on sm_103) ----
__device__ __forceinline__ uint32_t smem_u32(const void* p) {
    uint32_t a;
    asm("{ .reg .u64 t; cvta.to.shared.u64 t, %1; cvt.u32.u64 %0, t; }"
        : "=r"(a) : "l"(p));
    return a;
}
__device__ __forceinline__ uint32_t cvt2bf(float lo, float hi) {
    uint32_t r;
    asm("cvt.rn.bf16x2.f32 %0, %1, %2;" : "=r"(r) : "f"(hi), "f"(lo));
    return r;
}
__device__ __forceinline__ void ldm4(uint32_t* r, uint32_t addr) {
    asm volatile(
        "ldmatrix.sync.aligned.m8n8.x4.shared.b16 {%0,%1,%2,%3}, [%4];"
        : "=r"(r[0]), "=r"(r[1]), "=r"(r[2]), "=r"(r[3]) : "r"(addr));
}
__device__ __forceinline__ void mma_bf16(float* c, const uint32_t* a,
                                         uint32_t b0, uint32_t b1) {
    asm volatile(
        "mma.sync.aligned.m16n8k16.row.col.f32.bf16.bf16.f32 "
        "{%0,%1,%2,%3}, {%4,%5,%6,%7}, {%8,%9}, {%0,%1,%2,%3};"
        : "+f"(c[0]), "+f"(c[1]), "+f"(c[2]), "+f"(c[3])
        : "r"(a[0]), "r"(a[1]), "r"(a[2]), "r"(a[3]), "r"(b0), "r"(b1));
}

// ---------------------------------------------------------------------------
// wsplit: W[K,N] fp32 -> Wt1/Wt2[N,K] bf16 (transpose + 2-term split).
// Block (0,0) of the reset instance zeroes all barrier state.
// ---------------------------------------------------------------------------
__global__ __launch_bounds__(256) void wsplit(
    const float* __restrict__ W, __nv_bfloat16* __restrict__ Wt1,
    __nv_bfloat16* __restrict__ Wt2, int K, int N, int reset)
{
    __shared__ float tile[32][33];
    const int tx = threadIdx.x & 31, ty = threadIdx.x >> 5;
    const int bx = blockIdx.x, by = blockIdx.y;
    if (reset && bx == 0 && by == 0 && threadIdx.x == 0) {
#pragma unroll
        for (int g = 0; g < 2; g++) {
#pragma unroll
            for (int s = 0; s < 8; s++) g_barSub[g][s][0] = 0u;
            g_barRoot[g][0] = 0u;
        }
    }
    const int n = bx * 32 + tx;
#pragma unroll
    for (int i = 0; i < 4; i++) {
        int k = by * 32 + ty + i * 8;
        tile[ty + i * 8][tx] = W[(size_t)k * N + n];
    }
    __syncthreads();
    const int k2 = by * 32 + tx;
#pragma unroll
    for (int i = 0; i < 4; i++) {
        int n2 = bx * 32 + ty + i * 8;
        float v = tile[tx][ty + i * 8];
        __nv_bfloat16 b1 = __float2bfloat16_rn(v);
        float r = v - __bfloat162float(b1);
        Wt1[(size_t)n2 * K + k2] = b1;
        Wt2[(size_t)n2 * K + k2] = __float2bfloat16_rn(r);
    }
}

// ---------------------------------------------------------------------------
// mma_gemm (unchanged, proven R11): C = A(fp32) @ Wt + bias
// ---------------------------------------------------------------------------
#define AS1 0
#define AS2 18432
#define BS1 36864
#define BS2 46080
#define BIAS_OFF 55296
#define MM_SMEM 55552
#define RSTR 144

__global__ __launch_bounds__(256) void mma_gemm(
    const float* __restrict__ A,
    const __nv_bfloat16* __restrict__ Bt1,
    const __nv_bfloat16* __restrict__ Bt2,
    const float* __restrict__ bias, float* __restrict__ C,
    int M, int N, int K)
{
    extern __shared__ __align__(16) char ts[];
    const uint32_t sb = smem_u32(ts);
    float* sBias = (float*)(ts + BIAS_OFF);

    const int tid = threadIdx.x;
    const int wid = tid >> 5;
    const int lane = tid & 31;
    const int n0 = blockIdx.x * 64;
    const int m0 = blockIdx.y * 128;

    const int mw = (wid & 3) * 32;
    const int nw = (wid >> 2) * 32;
    const int l16 = lane & 15;
    const int lhi = lane >> 4;

    if (tid < 64) sBias[tid] = bias[n0 + tid];

    float acc[2][4][4];
#pragma unroll
    for (int i = 0; i < 2; i++)
#pragma unroll
        for (int j = 0; j < 4; j++)
#pragma unroll
            for (int q = 0; q < 4; q++) acc[i][j][q] = 0.0f;

    const int sr = tid >> 4;
    const int sc = tid & 15;
    const int br = tid >> 3;
    const int bc = tid & 7;

    const int nch = K >> 6;
    for (int c = 0; c < nch; ++c) {
        const int k0 = c << 6;
        if (c > 0) __syncthreads();

#pragma unroll
        for (int it = 0; it < 8; it++) {
            int r = sr + it * 16;
            float4 v = *(const float4*)(A + (size_t)(m0 + r) * K + k0 + sc * 4);
            uint32_t p1a = cvt2bf(v.x, v.y);
            uint32_t p1b = cvt2bf(v.z, v.w);
            float fx = v.x - __uint_as_float(p1a << 16);
            float fy = v.y - __uint_as_float(p1a & 0xFFFF0000u);
            float fz = v.z - __uint_as_float(p1b << 16);
            float fw = v.w - __uint_as_float(p1b & 0xFFFF0000u);
            uint32_t p2a = cvt2bf(fx, fy);
            uint32_t p2b = cvt2bf(fz, fw);
            uint32_t off = (uint32_t)(r * RSTR + sc * 8);
            *(unsigned long long*)(ts + AS1 + off) =
                (unsigned long long)p1a | ((unsigned long long)p1b << 32);
            *(unsigned long long*)(ts + AS2 + off) =
                (unsigned long long)p2a | ((unsigned long long)p2b << 32);
        }
#pragma unroll
        for (int it = 0; it < 2; it++) {
            int r = br + it * 32;
            size_t go = (size_t)(n0 + r) * K + k0 + bc * 8;
            uint4 v1 = *(const uint4*)(Bt1 + go);
            uint4 v2 = *(const uint4*)(Bt2 + go);
            uint32_t off = (uint32_t)(r * RSTR + bc * 16);
            *(uint4*)(ts + BS1 + off) = v1;
            *(uint4*)(ts + BS2 + off) = v2;
        }
        __syncthreads();

#pragma unroll
        for (int ks = 0; ks < 4; ks++) {
            const uint32_t kb = (uint32_t)((ks * 16 + lhi * 8) * 2);

            uint32_t a1[2][4], a2[2][4];
#pragma unroll
            for (int mf = 0; mf < 2; mf++) {
                uint32_t ao = (uint32_t)((mw + mf * 16 + l16) * RSTR) + kb;
                ldm4(a1[mf], sb + AS1 + ao);
                ldm4(a2[mf], sb + AS2 + ao);
            }
            uint32_t b1[2][4], b2[2][4];
#pragma unroll
            for (int np = 0; np < 2; np++) {
                uint32_t bo = (uint32_t)((nw + np * 16 + l16) * RSTR) + kb;
                ldm4(b1[np], sb + BS1 + bo);
                ldm4(b2[np], sb + BS2 + bo);
            }
#pragma unroll
            for (int mf = 0; mf < 2; mf++)
#pragma unroll
                for (int np = 0; np < 2; np++)
#pragma unroll
                    for (int hf = 0; hf < 2; hf++) {
                        float* cc = acc[mf][np * 2 + hf];
                        mma_bf16(cc, a1[mf], b1[np][hf], b1[np][hf + 2]);
                        mma_bf16(cc, a1[mf], b2[np][hf], b2[np][hf + 2]);
                        mma_bf16(cc, a2[mf], b1[np][hf], b1[np][hf + 2]);
                    }
        }
    }
    __syncthreads();

    const int g = lane >> 2;
    const int t = lane & 3;
#pragma unroll
    for (int mf = 0; mf < 2; mf++) {
#pragma unroll
        for (int nf = 0; nf < 4; nf++) {
            const int col = nw + nf * 8 + 2 * t;
            const float bx0 = sBias[col];
            const float bx1 = sBias[col + 1];
            const int row = m0 + mw + mf * 16 + g;
            float* cp = C + (size_t)row * N + n0 + col;
            float2 o0 = make_float2(acc[mf][nf][0] + bx0, acc[mf][nf][1] + bx1);
            float2 o1 = make_float2(acc[mf][nf][2] + bx0, acc[mf][nf][3] + bx1);
            *(float2*)cp = o0;
            *(float2*)(cp + (size_t)8 * N) = o1;
        }
    }
}

// ---------------------------------------------------------------------------
// Hierarchical group barrier: 64 CTAs/group = 8 subgroups x 8.
// Arrive: atom.acq_rel on own sub-counter; last of 8 releases into root.
// Wait: spin-acquire root until epoch*8.
// ---------------------------------------------------------------------------
__device__ __forceinline__ void grid_bar_h(unsigned* epoch, int tid, int grp,
                                           int sub) {
    __syncthreads();
    *epoch += 1;
    if (tid == 0) {
        unsigned old = atom_acqrel_add(&g_barSub[grp][sub][0], 1u);
        if (old == *epoch * 8u - 1u)
            red_release_add(&g_barRoot[grp][0], 1u);
        const unsigned tgt = *epoch * 8u;
        while (ld_acquire(&g_barRoot[grp][0]) < tgt) {}
    }
    __syncthreads();
}

// ---------------------------------------------------------------------------
// Recurrence (R8 layout, proven). 128 CTAs x 512 threads.
// ---------------------------------------------------------------------------
__global__ __launch_bounds__(512) void rnn_recurrence(
    const float* __restrict__ W_hh, float* __restrict__ states)
{
    extern __shared__ __align__(16) unsigned long long smu[];
    unsigned long long* Wd  = smu;            // [1024][16] u64   128 KB
    unsigned long long* Red = smu + RH * 16;  // [8][16][32] u64   32 KB

    const int tid = threadIdx.x;
    const int cid = blockIdx.x;
    const int n0 = (cid & 63) * 16;
    const int hb = cid >> 6;
    const int sub = cid & 7;
    const int lb = tid & 31;
    const int ks = tid >> 5;
    const int p  = lb & 15;
    const int jh = lb >> 4;

    for (int idx = tid; idx < RH * 16; idx += 512) {
        int k = idx >> 4, j = idx & 15;
        float w = W_hh[(size_t)k * RH + n0 + j];
        Wd[idx] = pack2(w, w);
    }
    __syncthreads();

    unsigned epoch = 0;

    {
        int j = tid >> 5, b = hb * 32 + (tid & 31);
        float* op = states + (size_t)b * RH + n0 + j;
        float v = tanhf(*op);
        *op = v;
        stcg32((float*)&g_hT[0][n0 + j][0] + b, v);
    }
    grid_bar_h(&epoch, tid, hb, sub);

    for (int t = 1; t < RT; ++t) {
        const float2* hp = &g_hT[(t - 1) & 1][ks * 64][hb * 16 + p];
        const unsigned long long* wp = Wd + (size_t)(ks * 64) * 16 + jh * 8;

        unsigned long long a[8];
#pragma unroll
        for (int c = 0; c < 8; c++) a[c] = 0ull;

        unsigned long long hbuf[8];
#pragma unroll
        for (int i = 0; i < 8; i++)
            hbuf[i] = ldcg64(hp + (size_t)i * 32);

#pragma unroll
        for (int blk = 0; blk < 8; blk++) {
            unsigned long long hcur[8];
#pragma unroll
            for (int i = 0; i < 8; i++) hcur[i] = hbuf[i];

            if (blk < 7) {
#pragma unroll
                for (int i = 0; i < 8; i++)
                    hbuf[i] = ldcg64(hp + (size_t)((blk + 1) * 8 + i) * 32);
            }

            const unsigned long long* wb = wp + (size_t)blk * 8 * 16;
#pragma unroll
            for (int i = 0; i < 8; i++) {
                ulonglong2 w01 = *(const ulonglong2*)(wb + i * 16);
                ulonglong2 w23 = *(const ulonglong2*)(wb + i * 16 + 2);
                ulonglong2 w45 = *(const ulonglong2*)(wb + i * 16 + 4);
                ulonglong2 w67 = *(const ulonglong2*)(wb + i * 16 + 6);
                unsigned long long h = hcur[i];
                a[0] = ffma2(h, w01.x, a[0]);
                a[1] = ffma2(h, w01.y, a[1]);
                a[2] = ffma2(h, w23.x, a[2]);
                a[3] = ffma2(h, w23.y, a[3]);
                a[4] = ffma2(h, w45.x, a[4]);
                a[5] = ffma2(h, w45.y, a[5]);
                a[6] = ffma2(h, w67.x, a[6]);
                a[7] = ffma2(h, w67.y, a[7]);
            }
        }

#pragma unroll
        for (int c = 0; c < 8; c++)
            Red[(size_t)c * 512 + ks * 32 + lb] = a[c];
        __syncthreads();

        if (tid < 256) {
            const int rp = tid & 15;
            const int rj = tid >> 4;
            const int rc = rj & 7;
            const int rh2 = rj >> 3;
            const unsigned long long* rsrc =
                Red + (size_t)rc * 512 + rh2 * 16 + rp;
            unsigned long long s = rsrc[0];
#pragma unroll
            for (int q = 1; q < 16; q++) s = add2(s, rsrc[(size_t)q * 32]);
            float2 f = unpack2(s);

            const int P = hb * 16 + rp;
            float* op0 = states + (size_t)t * (RB * RH) + (size_t)(2 * P) * RH + n0 + rj;
            float* op1 = op0 + RH;
            float v0 = tanhf(*op0 + f.x);
            float v1 = tanhf(*op1 + f.y);
            *op0 = v0;
            *op1 = v1;
            stcg64(&g_hT[t & 1][n0 + rj][P], pack2(v0, v1));
        }

        if (t < RT - 1) grid_bar_h(&epoch, tid, hb, sub);
    }
}

// ---------------------------------------------------------------------------
extern "C" void kernel_launch(void* const* d_in, const int* in_sizes, int n_in,
                              void* d_out, int out_size)
{
    const float* X    = (const float*)d_in[0];
    const float* W_xh = (const float*)d_in[1];
    const float* W_hh = (const float*)d_in[2];
    const float* b_h  = (const float*)d_in[3];
    const float* W_hq = (const float*)d_in[4];
    const float* b_q  = (const float*)d_in[5];

    float* outputs = (float*)d_out;                      // [T*B, O]
    float* states  = outputs + (size_t)RT * RB * RO;     // [T*B, H]

    const int M = RT * RB;  // 32768
    const int rec_smem = (RH * 16 + 8 * 16 * 32) * 8;    // 128KB + 32KB

    __nv_bfloat16 *pWxh1, *pWxh2, *pWhq1, *pWhq2;
    cudaGetSymbolAddress((void**)&pWxh1, g_Wxh1t);
    cudaGetSymbolAddress((void**)&pWxh2, g_Wxh2t);
    cudaGetSymbolAddress((void**)&pWhq1, g_Whq1t);
    cudaGetSymbolAddress((void**)&pWhq2, g_Whq2t);

    cudaFuncSetAttribute(rnn_recurrence,
                         cudaFuncAttributeMaxDynamicSharedMemorySize, rec_smem);
    cudaFuncSetAttribute(mma_gemm,
                         cudaFuncAttributeMaxDynamicSharedMemorySize, MM_SMEM);

    // W_xh[512,1024] -> Wt[1024,512]; resets barrier state
    wsplit<<<dim3(RH / 32, RI / 32), 256>>>(W_xh, pWxh1, pWxh2, RI, RH, 1);
    // W_hq[1024,512] -> Wt[512,1024]
    wsplit<<<dim3(RO / 32, RH / 32), 256>>>(W_hq, pWhq1, pWhq2, RH, RO, 0);

    // Xproj: states <- X @ W_xh + b_h   (M=32768, N=1024, K=512)
    mma_gemm<<<dim3(RH / 64, M / 128), 256, MM_SMEM>>>(
        X, pWxh1, pWxh2, b_h, states, M, RH, RI);

    rnn_recurrence<<<128, 512, rec_smem>>>(W_hh, states);

    // outputs <- states @ W_hq + b_q   (M=32768, N=512, K=1024)
    mma_gemm<<<dim3(RO / 64, M / 128), 256, MM_SMEM>>>(
        states, pWhq1, pWhq2, b_q, outputs, M, RO, RH);
}

// round 14
// speedup vs baseline: 1.5520x; 1.1211x over previous
#include <cuda_runtime.h>
#include <cuda_bf16.h>
#include <cstdint>

// ---------------------------------------------------------------------------
// RNN: h_t = tanh(X_t @ W_xh + b_h + h_{t-1} @ W_hh) ; y_t = h_t @ W_hq + b_q
// out = [outputs (T*B*O floats) | states (T*B*H floats)]
// T=512 B=64 H=1024 I=512 O=512
//
// R14: R11 base (mma.sync bf16 2-split GEMMs + scalar f32x2 recurrence), with
// the global grid barrier replaced by per-producer epoch flags: consumer warp
// ks depends on exactly 4 producer CTAs (cols 64ks..64ks+64); it spin-acquires
// only those. Ping-pong depth 2 proven safe (CTA enters epilogue t+1 only
// after all group flags >= t+1 => everyone finished reading h[t-1]).
// ---------------------------------------------------------------------------

#define RT 512
#define RB 64
#define RH 1024
#define RI 512
#define RO 512

// per-CTA epoch flags (one 128B line each): g_flag[cid][0] = steps completed
__device__ unsigned g_flag[128][32];

__device__ __align__(16) float2 g_hT[2][RH][RB / 2];
// split+transposed weights: Wt[n][k] bf16
__device__ __align__(16) __nv_bfloat16 g_Wxh1t[RH * RI];
__device__ __align__(16) __nv_bfloat16 g_Wxh2t[RH * RI];
__device__ __align__(16) __nv_bfloat16 g_Whq1t[RO * RH];
__device__ __align__(16) __nv_bfloat16 g_Whq2t[RO * RH];

// ---- scalar f32x2 helpers (recurrence) ----
__device__ __forceinline__ unsigned long long ffma2(unsigned long long a,
                                                    unsigned long long b,
                                                    unsigned long long c) {
    unsigned long long d;
    asm("fma.rn.f32x2 %0, %1, %2, %3;" : "=l"(d) : "l"(a), "l"(b), "l"(c));
    return d;
}
__device__ __forceinline__ unsigned long long add2(unsigned long long a,
                                                   unsigned long long b) {
    unsigned long long d;
    asm("add.rn.f32x2 %0, %1, %2;" : "=l"(d) : "l"(a), "l"(b));
    return d;
}
__device__ __forceinline__ unsigned long long pack2(float lo, float hi) {
    unsigned long long r;
    asm("mov.b64 %0, {%1, %2};" : "=l"(r) : "f"(lo), "f"(hi));
    return r;
}
__device__ __forceinline__ float2 unpack2(unsigned long long v) {
    float lo, hi;
    asm("mov.b64 {%0, %1}, %2;" : "=f"(lo), "=f"(hi) : "l"(v));
    return make_float2(lo, hi);
}
__device__ __forceinline__ unsigned long long ldcg64(const void* p) {
    unsigned long long v;
    asm volatile("ld.global.cg.b64 %0, [%1];" : "=l"(v) : "l"(p));
    return v;
}
__device__ __forceinline__ void stcg32(float* p, float v) {
    asm volatile("st.global.cg.f32 [%0], %1;" :: "l"(p), "f"(v));
}
__device__ __forceinline__ void stcg64(void* p, unsigned long long v) {
    asm volatile("st.global.cg.b64 [%0], %1;" :: "l"(p), "l"(v));
}
__device__ __forceinline__ void red_release_add(unsigned* p, unsigned v) {
    asm volatile("red.release.gpu.global.add.u32 [%0], %1;" :: "l"(p), "r"(v)
                 : "memory");
}
__device__ __forceinline__ unsigned ld_acquire(const unsigned* p) {
    unsigned v;
    asm volatile("ld.acquire.gpu.global.u32 %0, [%1];" : "=r"(v) : "l"(p)
                 : "memory");
    return v;
}

// ---- tensor-core helpers (baseline PTX: sm_80+, valid on sm_103) ----
__device__ __forceinline__ uint32_t smem_u32(const void* p) {
    uint32_t a;
    asm("{ .reg .u64 t; cvta.to.shared.u64 t, %1; cvt.u32.u64 %0, t; }"
        : "=r"(a) : "l"(p));
    return a;
}
__device__ __forceinline__ uint32_t cvt2bf(float lo, float hi) {
    uint32_t r;
    asm("cvt.rn.bf16x2.f32 %0, %1, %2;" : "=r"(r) : "f"(hi), "f"(lo));
    return r;
}
__device__ __forceinline__ void ldm4(uint32_t* r, uint32_t addr) {
    asm volatile(
        "ldmatrix.sync.aligned.m8n8.x4.shared.b16 {%0,%1,%2,%3}, [%4];"
        : "=r"(r[0]), "=r"(r[1]), "=r"(r[2]), "=r"(r[3]) : "r"(addr));
}
__device__ __forceinline__ void mma_bf16(float* c, const uint32_t* a,
                                         uint32_t b0, uint32_t b1) {
    asm volatile(
        "mma.sync.aligned.m16n8k16.row.col.f32.bf16.bf16.f32 "
        "{%0,%1,%2,%3}, {%4,%5,%6,%7}, {%8,%9}, {%0,%1,%2,%3};"
        : "+f"(c[0]), "+f"(c[1]), "+f"(c[2]), "+f"(c[3])
        : "r"(a[0]), "r"(a[1]), "r"(a[2]), "r"(a[3]), "r"(b0), "r"(b1));
}

// ---------------------------------------------------------------------------
// wsplit: W[K,N] fp32 -> Wt1/Wt2[N,K] bf16 (transpose + 2-term split).
// Block (0,0) of the reset instance zeroes all flag state.
// ---------------------------------------------------------------------------
__global__ __launch_bounds__(256) void wsplit(
    const float* __restrict__ W, __nv_bfloat16* __restrict__ Wt1,
    __nv_bfloat16* __restrict__ Wt2, int K, int N, int reset)
{
    __shared__ float tile[32][33];
    const int tx = threadIdx.x & 31, ty = threadIdx.x >> 5;
    const int bx = blockIdx.x, by = blockIdx.y;
    if (reset && bx == 0 && by == 0 && ty == 0) {
#pragma unroll
        for (int c = tx; c < 128; c += 32) g_flag[c][0] = 0u;
    }
    const int n = bx * 32 + tx;
#pragma unroll
    for (int i = 0; i < 4; i++) {
        int k = by * 32 + ty + i * 8;
        tile[ty + i * 8][tx] = W[(size_t)k * N + n];
    }
    __syncthreads();
    const int k2 = by * 32 + tx;
#pragma unroll
    for (int i = 0; i < 4; i++) {
        int n2 = bx * 32 + ty + i * 8;
        float v = tile[tx][ty + i * 8];
        __nv_bfloat16 b1 = __float2bfloat16_rn(v);
        float r = v - __bfloat162float(b1);
        Wt1[(size_t)n2 * K + k2] = b1;
        Wt2[(size_t)n2 * K + k2] = __float2bfloat16_rn(r);
    }
}

// ---------------------------------------------------------------------------
// mma_gemm (unchanged, proven R11): C = A(fp32) @ Wt + bias
// ---------------------------------------------------------------------------
#define AS1 0
#define AS2 18432
#define BS1 36864
#define BS2 46080
#define BIAS_OFF 55296
#define MM_SMEM 55552
#define RSTR 144

__global__ __launch_bounds__(256) void mma_gemm(
    const float* __restrict__ A,
    const __nv_bfloat16* __restrict__ Bt1,
    const __nv_bfloat16* __restrict__ Bt2,
    const float* __restrict__ bias, float* __restrict__ C,
    int M, int N, int K)
{
    extern __shared__ __align__(16) char ts[];
    const uint32_t sb = smem_u32(ts);
    float* sBias = (float*)(ts + BIAS_OFF);

    const int tid = threadIdx.x;
    const int wid = tid >> 5;
    const int lane = tid & 31;
    const int n0 = blockIdx.x * 64;
    const int m0 = blockIdx.y * 128;

    const int mw = (wid & 3) * 32;
    const int nw = (wid >> 2) * 32;
    const int l16 = lane & 15;
    const int lhi = lane >> 4;

    if (tid < 64) sBias[tid] = bias[n0 + tid];

    float acc[2][4][4];
#pragma unroll
    for (int i = 0; i < 2; i++)
#pragma unroll
        for (int j = 0; j < 4; j++)
#pragma unroll
            for (int q = 0; q < 4; q++) acc[i][j][q] = 0.0f;

    const int sr = tid >> 4;
    const int sc = tid & 15;
    const int br = tid >> 3;
    const int bc = tid & 7;

    const int nch = K >> 6;
    for (int c = 0; c < nch; ++c) {
        const int k0 = c << 6;
        if (c > 0) __syncthreads();

#pragma unroll
        for (int it = 0; it < 8; it++) {
            int r = sr + it * 16;
            float4 v = *(const float4*)(A + (size_t)(m0 + r) * K + k0 + sc * 4);
            uint32_t p1a = cvt2bf(v.x, v.y);
            uint32_t p1b = cvt2bf(v.z, v.w);
            float fx = v.x - __uint_as_float(p1a << 16);
            float fy = v.y - __uint_as_float(p1a & 0xFFFF0000u);
            float fz = v.z - __uint_as_float(p1b << 16);
            float fw = v.w - __uint_as_float(p1b & 0xFFFF0000u);
            uint32_t p2a = cvt2bf(fx, fy);
            uint32_t p2b = cvt2bf(fz, fw);
            uint32_t off = (uint32_t)(r * RSTR + sc * 8);
            *(unsigned long long*)(ts + AS1 + off) =
                (unsigned long long)p1a | ((unsigned long long)p1b << 32);
            *(unsigned long long*)(ts + AS2 + off) =
                (unsigned long long)p2a | ((unsigned long long)p2b << 32);
        }
#pragma unroll
        for (int it = 0; it < 2; it++) {
            int r = br + it * 32;
            size_t go = (size_t)(n0 + r) * K + k0 + bc * 8;
            uint4 v1 = *(const uint4*)(Bt1 + go);
            uint4 v2 = *(const uint4*)(Bt2 + go);
            uint32_t off = (uint32_t)(r * RSTR + bc * 16);
            *(uint4*)(ts + BS1 + off) = v1;
            *(uint4*)(ts + BS2 + off) = v2;
        }
        __syncthreads();

#pragma unroll
        for (int ks = 0; ks < 4; ks++) {
            const uint32_t kb = (uint32_t)((ks * 16 + lhi * 8) * 2);

            uint32_t a1[2][4], a2[2][4];
#pragma unroll
            for (int mf = 0; mf < 2; mf++) {
                uint32_t ao = (uint32_t)((mw + mf * 16 + l16) * RSTR) + kb;
                ldm4(a1[mf], sb + AS1 + ao);
                ldm4(a2[mf], sb + AS2 + ao);
            }
            uint32_t b1[2][4], b2[2][4];
#pragma unroll
            for (int np = 0; np < 2; np++) {
                uint32_t bo = (uint32_t)((nw + np * 16 + l16) * RSTR) + kb;
                ldm4(b1[np], sb + BS1 + bo);
                ldm4(b2[np], sb + BS2 + bo);
            }
#pragma unroll
            for (int mf = 0; mf < 2; mf++)
#pragma unroll
                for (int np = 0; np < 2; np++)
#pragma unroll
                    for (int hf = 0; hf < 2; hf++) {
                        float* cc = acc[mf][np * 2 + hf];
                        mma_bf16(cc, a1[mf], b1[np][hf], b1[np][hf + 2]);
                        mma_bf16(cc, a1[mf], b2[np][hf], b2[np][hf + 2]);
                        mma_bf16(cc, a2[mf], b1[np][hf], b1[np][hf + 2]);
                    }
        }
    }
    __syncthreads();

    const int g = lane >> 2;
    const int t = lane & 3;
#pragma unroll
    for (int mf = 0; mf < 2; mf++) {
#pragma unroll
        for (int nf = 0; nf < 4; nf++) {
            const int col = nw + nf * 8 + 2 * t;
            const float bx0 = sBias[col];
            const float bx1 = sBias[col + 1];
            const int row = m0 + mw + mf * 16 + g;
            float* cp = C + (size_t)row * N + n0 + col;
            float2 o0 = make_float2(acc[mf][nf][0] + bx0, acc[mf][nf][1] + bx1);
            float2 o1 = make_float2(acc[mf][nf][2] + bx0, acc[mf][nf][3] + bx1);
            *(float2*)cp = o0;
            *(float2*)(cp + (size_t)8 * N) = o1;
        }
    }
}

// ---------------------------------------------------------------------------
// Recurrence (R11 layout; barrier replaced by per-producer epoch flags).
// 128 CTAs x 512 threads. CTA cid: cols n0=(cid&63)*16, batch half hb=cid>>6.
// Warp ks reads h k-slice [64ks,64ks+64) -> depends on producer CTAs
// hb*64 + 4ks + {0,1,2,3}. Lanes 0-3 each spin-acquire one flag.
// ---------------------------------------------------------------------------
__global__ __launch_bounds__(512) void rnn_recurrence(
    const float* __restrict__ W_hh, float* __restrict__ states)
{
    extern __shared__ __align__(16) unsigned long long smu[];
    unsigned long long* Wd  = smu;            // [1024][16] u64   128 KB
    unsigned long long* Red = smu + RH * 16;  // [8][16][32] u64   32 KB

    const int tid = threadIdx.x;
    const int cid = blockIdx.x;
    const int n0 = (cid & 63) * 16;
    const int hb = cid >> 6;
    const int lb = tid & 31;
    const int ks = tid >> 5;
    const int p  = lb & 15;
    const int jh = lb >> 4;

    // this warp's producer flag (lanes 0-3 poll; others ignore)
    unsigned* myflag = &g_flag[hb * 64 + 4 * ks + (lb & 3)][0];

    for (int idx = tid; idx < RH * 16; idx += 512) {
        int k = idx >> 4, j = idx & 15;
        float w = W_hh[(size_t)k * RH + n0 + j];
        Wd[idx] = pack2(w, w);
    }
    __syncthreads();

    // t = 0: h_0 = tanh(xp); write states + hT[0]; publish flag = 1
    {
        int j = tid >> 5, b = hb * 32 + (tid & 31);
        float* op = states + (size_t)b * RH + n0 + j;
        float v = tanhf(*op);
        *op = v;
        stcg32((float*)&g_hT[0][n0 + j][0] + b, v);
    }
    __syncthreads();
    if (tid == 0) red_release_add(&g_flag[cid][0], 1u);

    for (int t = 1; t < RT; ++t) {
        // per-warp producer wait: lanes 0-3 spin-acquire their producer's flag
        if (lb < 4) {
            while (ld_acquire(myflag) < (unsigned)t) {}
        }
        __syncwarp();

        const float2* hp = &g_hT[(t - 1) & 1][ks * 64][hb * 16 + p];
        const unsigned long long* wp = Wd + (size_t)(ks * 64) * 16 + jh * 8;

        unsigned long long a[8];
#pragma unroll
        for (int c = 0; c < 8; c++) a[c] = 0ull;

        unsigned long long hbuf[8];
#pragma unroll
        for (int i = 0; i < 8; i++)
            hbuf[i] = ldcg64(hp + (size_t)i * 32);

#pragma unroll
        for (int blk = 0; blk < 8; blk++) {
            unsigned long long hcur[8];
#pragma unroll
            for (int i = 0; i < 8; i++) hcur[i] = hbuf[i];

            if (blk < 7) {
#pragma unroll
                for (int i = 0; i < 8; i++)
                    hbuf[i] = ldcg64(hp + (size_t)((blk + 1) * 8 + i) * 32);
            }

            const unsigned long long* wb = wp + (size_t)blk * 8 * 16;
#pragma unroll
            for (int i = 0; i < 8; i++) {
                ulonglong2 w01 = *(const ulonglong2*)(wb + i * 16);
                ulonglong2 w23 = *(const ulonglong2*)(wb + i * 16 + 2);
                ulonglong2 w45 = *(const ulonglong2*)(wb + i * 16 + 4);
                ulonglong2 w67 = *(const ulonglong2*)(wb + i * 16 + 6);
                unsigned long long h = hcur[i];
                a[0] = ffma2(h, w01.x, a[0]);
                a[1] = ffma2(h, w01.y, a[1]);
                a[2] = ffma2(h, w23.x, a[2]);
                a[3] = ffma2(h, w23.y, a[3]);
                a[4] = ffma2(h, w45.x, a[4]);
                a[5] = ffma2(h, w45.y, a[5]);
                a[6] = ffma2(h, w67.x, a[6]);
                a[7] = ffma2(h, w67.y, a[7]);
            }
        }

#pragma unroll
        for (int c = 0; c < 8; c++)
            Red[(size_t)c * 512 + ks * 32 + lb] = a[c];
        __syncthreads();

        if (tid < 256) {
            const int rp = tid & 15;
            const int rj = tid >> 4;
            const int rc = rj & 7;
            const int rh2 = rj >> 3;
            const unsigned long long* rsrc =
                Red + (size_t)rc * 512 + rh2 * 16 + rp;
            unsigned long long s = rsrc[0];
#pragma unroll
            for (int q = 1; q < 16; q++) s = add2(s, rsrc[(size_t)q * 32]);
            float2 f = unpack2(s);

            const int P = hb * 16 + rp;
            float* op0 = states + (size_t)t * (RB * RH) + (size_t)(2 * P) * RH + n0 + rj;
            float* op1 = op0 + RH;
            float v0 = tanhf(*op0 + f.x);
            float v1 = tanhf(*op1 + f.y);
            *op0 = v0;
            *op1 = v1;
            stcg64(&g_hT[t & 1][n0 + rj][P], pack2(v0, v1));
        }
        __syncthreads();

        // publish: this CTA finished step t
        if (tid == 0 && t < RT - 1) red_release_add(&g_flag[cid][0], 1u);
    }
}

// ---------------------------------------------------------------------------
extern "C" void kernel_launch(void* const* d_in, const int* in_sizes, int n_in,
                              void* d_out, int out_size)
{
    const float* X    = (const float*)d_in[0];
    const float* W_xh = (const float*)d_in[1];
    const float* W_hh = (const float*)d_in[2];
    const float* b_h  = (const float*)d_in[3];
    const float* W_hq = (const float*)d_in[4];
    const float* b_q  = (const float*)d_in[5];

    float* outputs = (float*)d_out;                      // [T*B, O]
    float* states  = outputs + (size_t)RT * RB * RO;     // [T*B, H]

    const int M = RT * RB;  // 32768
    const int rec_smem = (RH * 16 + 8 * 16 * 32) * 8;    // 128KB + 32KB

    __nv_bfloat16 *pWxh1, *pWxh2, *pWhq1, *pWhq2;
    cudaGetSymbolAddress((void**)&pWxh1, g_Wxh1t);
    cudaGetSymbolAddress((void**)&pWxh2, g_Wxh2t);
    cudaGetSymbolAddress((void**)&pWhq1, g_Whq1t);
    cudaGetSymbolAddress((void**)&pWhq2, g_Whq2t);

    cudaFuncSetAttribute(rnn_recurrence,
                         cudaFuncAttributeMaxDynamicSharedMemorySize, rec_smem);
    cudaFuncSetAttribute(mma_gemm,
                         cudaFuncAttributeMaxDynamicSharedMemorySize, MM_SMEM);

    // W_xh[512,1024] -> Wt[1024,512]; resets flag state
    wsplit<<<dim3(RH / 32, RI / 32), 256>>>(W_xh, pWxh1, pWxh2, RI, RH, 1);
    // W_hq[1024,512] -> Wt[512,1024]
    wsplit<<<dim3(RO / 32, RH / 32), 256>>>(W_hq, pWhq1, pWhq2, RH, RO, 0);

    // Xproj: states <- X @ W_xh + b_h   (M=32768, N=1024, K=512)
    mma_gemm<<<dim3(RH / 64, M / 128), 256, MM_SMEM>>>(
        X, pWxh1, pWxh2, b_h, states, M, RH, RI);

    rnn_recurrence<<<128, 512, rec_smem>>>(W_hh, states);

    // outputs <- states @ W_hq + b_q   (M=32768, N=512, K=1024)
    mma_gemm<<<dim3(RO / 64, M / 128), 256, MM_SMEM>>>(
        states, pWhq1, pWhq2, b_q, outputs, M, RO, RH);
}

// round 15
// speedup vs baseline: 2.1082x; 1.3584x over previous
#include <cuda_runtime.h>
#include <cuda_bf16.h>
#include <cstdint>

// ---------------------------------------------------------------------------
// RNN: h_t = tanh(X_t @ W_xh + b_h + h_{t-1} @ W_hh) ; y_t = h_t @ W_hq + b_q
// out = [outputs (T*B*O floats) | states (T*B*H floats)]
// T=512 B=64 H=1024 I=512 O=512
//
// R15: tensorized recurrence v2 — producers write h DIRECTLY in mma A-frag
// layout (1 STG.32/split/thread), consumers LDG.128 fragments straight into
// registers (no smem staging, no chunk syncs). W_hh frags hoisted to regs.
// Per-producer flag sync (R14, proven). GEMMs unchanged (R11, proven).
// ---------------------------------------------------------------------------

#define RT 512
#define RB 64
#define RH 1024
#define RI 512
#define RO 512

// per-CTA epoch flags (one 128B line each)
__device__ unsigned g_flag[128][32];
// h in mma A-frag layout: [pingpong][split][(ktile*4+mtile)*32+lane][q]
__device__ __align__(16) uint32_t g_hA[2][2][256 * 32 * 4];
// split+transposed weights: Wt[n][k] bf16
__device__ __align__(16) __nv_bfloat16 g_Wxh1t[RH * RI];
__device__ __align__(16) __nv_bfloat16 g_Wxh2t[RH * RI];
__device__ __align__(16) __nv_bfloat16 g_Whq1t[RO * RH];
__device__ __align__(16) __nv_bfloat16 g_Whq2t[RO * RH];
__device__ __align__(16) __nv_bfloat16 g_Whh1t[RH * RH];
__device__ __align__(16) __nv_bfloat16 g_Whh2t[RH * RH];

// ---- helpers ----
__device__ __forceinline__ unsigned long long pack2(float lo, float hi) {
    unsigned long long r;
    asm("mov.b64 %0, {%1, %2};" : "=l"(r) : "f"(lo), "f"(hi));
    return r;
}
__device__ __forceinline__ float2 unpack2(unsigned long long v) {
    float lo, hi;
    asm("mov.b64 {%0, %1}, %2;" : "=f"(lo), "=f"(hi) : "l"(v));
    return make_float2(lo, hi);
}
__device__ __forceinline__ unsigned long long add2(unsigned long long a,
                                                   unsigned long long b) {
    unsigned long long d;
    asm("add.rn.f32x2 %0, %1, %2;" : "=l"(d) : "l"(a), "l"(b));
    return d;
}
__device__ __forceinline__ void stcg32u(void* p, uint32_t v) {
    asm volatile("st.global.cg.u32 [%0], %1;" :: "l"(p), "r"(v));
}
__device__ __forceinline__ uint4 ldcg128(const void* p) {
    uint4 v;
    asm volatile("ld.global.cg.v4.u32 {%0,%1,%2,%3}, [%4];"
                 : "=r"(v.x), "=r"(v.y), "=r"(v.z), "=r"(v.w) : "l"(p));
    return v;
}
__device__ __forceinline__ void red_release_add(unsigned* p, unsigned v) {
    asm volatile("red.release.gpu.global.add.u32 [%0], %1;" :: "l"(p), "r"(v)
                 : "memory");
}
__device__ __forceinline__ unsigned ld_acquire(const unsigned* p) {
    unsigned v;
    asm volatile("ld.acquire.gpu.global.u32 %0, [%1];" : "=r"(v) : "l"(p)
                 : "memory");
    return v;
}
__device__ __forceinline__ uint32_t smem_u32(const void* p) {
    uint32_t a;
    asm("{ .reg .u64 t; cvta.to.shared.u64 t, %1; cvt.u32.u64 %0, t; }"
        : "=r"(a) : "l"(p));
    return a;
}
__device__ __forceinline__ uint32_t cvt2bf(float lo, float hi) {
    uint32_t r;
    asm("cvt.rn.bf16x2.f32 %0, %1, %2;" : "=r"(r) : "f"(hi), "f"(lo));
    return r;
}
__device__ __forceinline__ void ldm4(uint32_t* r, uint32_t addr) {
    asm volatile(
        "ldmatrix.sync.aligned.m8n8.x4.shared.b16 {%0,%1,%2,%3}, [%4];"
        : "=r"(r[0]), "=r"(r[1]), "=r"(r[2]), "=r"(r[3]) : "r"(addr));
}
__device__ __forceinline__ void mma_bf16(float* c, const uint32_t* a,
                                         uint32_t b0, uint32_t b1) {
    asm volatile(
        "mma.sync.aligned.m16n8k16.row.col.f32.bf16.bf16.f32 "
        "{%0,%1,%2,%3}, {%4,%5,%6,%7}, {%8,%9}, {%0,%1,%2,%3};"
        : "+f"(c[0]), "+f"(c[1]), "+f"(c[2]), "+f"(c[3])
        : "r"(a[0]), "r"(a[1]), "r"(a[2]), "r"(a[3]), "r"(b0), "r"(b1));
}

// ---------------------------------------------------------------------------
// wsplit: W[K,N] fp32 -> Wt1/Wt2[N,K] bf16 (transpose + 2-term split).
// ---------------------------------------------------------------------------
__global__ __launch_bounds__(256) void wsplit(
    const float* __restrict__ W, __nv_bfloat16* __restrict__ Wt1,
    __nv_bfloat16* __restrict__ Wt2, int K, int N, int reset)
{
    __shared__ float tile[32][33];
    const int tx = threadIdx.x & 31, ty = threadIdx.x >> 5;
    const int bx = blockIdx.x, by = blockIdx.y;
    if (reset && bx == 0 && by == 0 && ty == 0) {
#pragma unroll
        for (int c = tx; c < 128; c += 32) g_flag[c][0] = 0u;
    }
    const int n = bx * 32 + tx;
#pragma unroll
    for (int i = 0; i < 4; i++) {
        int k = by * 32 + ty + i * 8;
        tile[ty + i * 8][tx] = W[(size_t)k * N + n];
    }
    __syncthreads();
    const int k2 = by * 32 + tx;
#pragma unroll
    for (int i = 0; i < 4; i++) {
        int n2 = bx * 32 + ty + i * 8;
        float v = tile[tx][ty + i * 8];
        __nv_bfloat16 b1 = __float2bfloat16_rn(v);
        float r = v - __bfloat162float(b1);
        Wt1[(size_t)n2 * K + k2] = b1;
        Wt2[(size_t)n2 * K + k2] = __float2bfloat16_rn(r);
    }
}

// ---------------------------------------------------------------------------
// mma_gemm (unchanged, proven R11): C = A(fp32) @ Wt + bias
// ---------------------------------------------------------------------------
#define AS1 0
#define AS2 18432
#define BS1 36864
#define BS2 46080
#define BIAS_OFF 55296
#define MM_SMEM 55552
#define RSTR 144

__global__ __launch_bounds__(256) void mma_gemm(
    const float* __restrict__ A,
    const __nv_bfloat16* __restrict__ Bt1,
    const __nv_bfloat16* __restrict__ Bt2,
    const float* __restrict__ bias, float* __restrict__ C,
    int M, int N, int K)
{
    extern __shared__ __align__(16) char ts[];
    const uint32_t sb = smem_u32(ts);
    float* sBias = (float*)(ts + BIAS_OFF);

    const int tid = threadIdx.x;
    const int wid = tid >> 5;
    const int lane = tid & 31;
    const int n0 = blockIdx.x * 64;
    const int m0 = blockIdx.y * 128;

    const int mw = (wid & 3) * 32;
    const int nw = (wid >> 2) * 32;
    const int l16 = lane & 15;
    const int lhi = lane >> 4;

    if (tid < 64) sBias[tid] = bias[n0 + tid];

    float acc[2][4][4];
#pragma unroll
    for (int i = 0; i < 2; i++)
#pragma unroll
        for (int j = 0; j < 4; j++)
#pragma unroll
            for (int q = 0; q < 4; q++) acc[i][j][q] = 0.0f;

    const int sr = tid >> 4;
    const int sc = tid & 15;
    const int br = tid >> 3;
    const int bc = tid & 7;

    const int nch = K >> 6;
    for (int c = 0; c < nch; ++c) {
        const int k0 = c << 6;
        if (c > 0) __syncthreads();

#pragma unroll
        for (int it = 0; it < 8; it++) {
            int r = sr + it * 16;
            float4 v = *(const float4*)(A + (size_t)(m0 + r) * K + k0 + sc * 4);
            uint32_t p1a = cvt2bf(v.x, v.y);
            uint32_t p1b = cvt2bf(v.z, v.w);
            float fx = v.x - __uint_as_float(p1a << 16);
            float fy = v.y - __uint_as_float(p1a & 0xFFFF0000u);
            float fz = v.z - __uint_as_float(p1b << 16);
            float fw = v.w - __uint_as_float(p1b & 0xFFFF0000u);
            uint32_t p2a = cvt2bf(fx, fy);
            uint32_t p2b = cvt2bf(fz, fw);
            uint32_t off = (uint32_t)(r * RSTR + sc * 8);
            *(unsigned long long*)(ts + AS1 + off) =
                (unsigned long long)p1a | ((unsigned long long)p1b << 32);
            *(unsigned long long*)(ts + AS2 + off) =
                (unsigned long long)p2a | ((unsigned long long)p2b << 32);
        }
#pragma unroll
        for (int it = 0; it < 2; it++) {
            int r = br + it * 32;
            size_t go = (size_t)(n0 + r) * K + k0 + bc * 8;
            uint4 v1 = *(const uint4*)(Bt1 + go);
            uint4 v2 = *(const uint4*)(Bt2 + go);
            uint32_t off = (uint32_t)(r * RSTR + bc * 16);
            *(uint4*)(ts + BS1 + off) = v1;
            *(uint4*)(ts + BS2 + off) = v2;
        }
        __syncthreads();

#pragma unroll
        for (int ks = 0; ks < 4; ks++) {
            const uint32_t kb = (uint32_t)((ks * 16 + lhi * 8) * 2);

            uint32_t a1[2][4], a2[2][4];
#pragma unroll
            for (int mf = 0; mf < 2; mf++) {
                uint32_t ao = (uint32_t)((mw + mf * 16 + l16) * RSTR) + kb;
                ldm4(a1[mf], sb + AS1 + ao);
                ldm4(a2[mf], sb + AS2 + ao);
            }
            uint32_t b1[2][4], b2[2][4];
#pragma unroll
            for (int np = 0; np < 2; np++) {
                uint32_t bo = (uint32_t)((nw + np * 16 + l16) * RSTR) + kb;
                ldm4(b1[np], sb + BS1 + bo);
                ldm4(b2[np], sb + BS2 + bo);
            }
#pragma unroll
            for (int mf = 0; mf < 2; mf++)
#pragma unroll
                for (int np = 0; np < 2; np++)
#pragma unroll
                    for (int hf = 0; hf < 2; hf++) {
                        float* cc = acc[mf][np * 2 + hf];
                        mma_bf16(cc, a1[mf], b1[np][hf], b1[np][hf + 2]);
                        mma_bf16(cc, a1[mf], b2[np][hf], b2[np][hf + 2]);
                        mma_bf16(cc, a2[mf], b1[np][hf], b1[np][hf + 2]);
                    }
        }
    }
    __syncthreads();

    const int g = lane >> 2;
    const int t = lane & 3;
#pragma unroll
    for (int mf = 0; mf < 2; mf++) {
#pragma unroll
        for (int nf = 0; nf < 4; nf++) {
            const int col = nw + nf * 8 + 2 * t;
            const float bx0 = sBias[col];
            const float bx1 = sBias[col + 1];
            const int row = m0 + mw + mf * 16 + g;
            float* cp = C + (size_t)row * N + n0 + col;
            float2 o0 = make_float2(acc[mf][nf][0] + bx0, acc[mf][nf][1] + bx1);
            float2 o1 = make_float2(acc[mf][nf][2] + bx0, acc[mf][nf][3] + bx1);
            *(float2*)cp = o0;
            *(float2*)(cp + (size_t)8 * N) = o1;
        }
    }
}

// ---------------------------------------------------------------------------
// rnn_rec_mma: tensorized recurrence. 128 CTAs x 512 threads (16 warps).
// CTA cid: cols n0=(cid&63)*16 (= ktile cid&63), batch half hb=cid>>6.
// Warp ks covers k in [64ks, 64ks+64) = ktiles 4ks..4ks+3 -> producers
// hb*64 + 4ks + {0..3}. W_hh frags hoisted to registers (loop-invariant).
// Red[ks 16][slot 8][lane 32] u64; 256-thread 16-way add2 reduce + epilogue
// writes states + h in A-frag layout (frag lane == epilogue lane).
// ---------------------------------------------------------------------------
#define RW1 0
#define RW2 33024
#define RREDB 66048
#define REC_SMEM 98816

__global__ __launch_bounds__(512) void rnn_rec_mma(
    const __nv_bfloat16* __restrict__ Whh1,
    const __nv_bfloat16* __restrict__ Whh2,
    float* __restrict__ states)
{
    extern __shared__ __align__(16) char rs[];
    const uint32_t sb = smem_u32(rs);
    unsigned long long* Red = (unsigned long long*)(rs + RREDB);

    const int tid = threadIdx.x;
    const int ks = tid >> 5;
    const int lane = tid & 31;
    const int cid = blockIdx.x;
    const int hb = cid >> 6;
    const int kt_self = cid & 63;
    const int n0 = kt_self * 16;

    unsigned* myflag = &g_flag[hb * 64 + 4 * ks + (lane & 3)][0];

    // one-time: W_hh slice [16 n][1024 k] x2 splits into smem (stride 2064)
    for (int idx = tid; idx < 16 * 128; idx += 512) {
        int r = idx >> 7, c = idx & 127;
        *(uint4*)(rs + RW1 + r * 2064 + c * 16) =
            *(const uint4*)(Whh1 + (size_t)(n0 + r) * RH + c * 8);
        *(uint4*)(rs + RW2 + r * 2064 + c * 16) =
            *(const uint4*)(Whh2 + (size_t)(n0 + r) * RH + c * 8);
    }
    __syncthreads();

    // hoist W frags: 4 ktiles x 2 splits (B-frag source, proven ldmatrix path)
    uint32_t wf1[4][4], wf2[4][4];
#pragma unroll
    for (int kt = 0; kt < 4; kt++) {
        uint32_t bo = (uint32_t)((lane & 15) * 2064 +
                                 ((ks * 4 + kt) * 16 + (lane >> 4) * 8) * 2);
        ldm4(wf1[kt], sb + RW1 + bo);
        ldm4(wf2[kt], sb + RW2 + bo);
    }

    // t = 0: h_0 = tanh(xp); epilogue mapping (slot s, lane l)
    if (tid < 256) {
        const int l = tid & 31, s = tid >> 5;
        const int mtl = s >> 2, nt = (s >> 1) & 1, rr = s & 1;
        const int row = hb * 32 + mtl * 16 + rr * 8 + (l >> 2);
        const int col = n0 + nt * 8 + 2 * (l & 3);
        float* op = states + (size_t)row * RH + col;
        float2 xp = *(float2*)op;
        float v0 = tanhf(xp.x), v1 = tanhf(xp.y);
        *(float2*)op = make_float2(v0, v1);
        uint32_t q1 = cvt2bf(v0, v1);
        float e0 = v0 - __uint_as_float(q1 << 16);
        float e1 = v1 - __uint_as_float(q1 & 0xFFFF0000u);
        uint32_t idx = (uint32_t)(((kt_self * 4 + hb * 2 + mtl) * 32 + l) * 4 +
                                  rr + 2 * nt);
        stcg32u(&g_hA[0][0][idx], q1);
        stcg32u(&g_hA[0][1][idx], cvt2bf(e0, e1));
    }
    __syncthreads();
    if (tid == 0) red_release_add(&g_flag[cid][0], 1u);

    for (int t = 1; t < RT; ++t) {
        const int pp_r = (t - 1) & 1;

        if ((lane & 31) < 4) {
            while (ld_acquire(myflag) < (unsigned)t) {}
        }
        __syncwarp();

        float acc[2][2][4];
#pragma unroll
        for (int mt = 0; mt < 2; mt++)
#pragma unroll
            for (int nt = 0; nt < 2; nt++)
#pragma unroll
                for (int q = 0; q < 4; q++) acc[mt][nt][q] = 0.0f;

#pragma unroll
        for (int mt = 0; mt < 2; mt++) {
            // load this mtile's A frags for all 4 ktiles, both splits
            uint4 A1[4], A2[4];
#pragma unroll
            for (int kt = 0; kt < 4; kt++) {
                uint32_t base = (uint32_t)((((ks * 4 + kt) * 4 + hb * 2 + mt) * 32
                                            + lane) * 4);
                A1[kt] = ldcg128(&g_hA[pp_r][0][base]);
                A2[kt] = ldcg128(&g_hA[pp_r][1][base]);
            }
#pragma unroll
            for (int kt = 0; kt < 4; kt++) {
#pragma unroll
                for (int nt = 0; nt < 2; nt++) {
                    float* cc = acc[mt][nt];
                    mma_bf16(cc, (const uint32_t*)&A1[kt], wf1[kt][nt], wf1[kt][nt + 2]);
                    mma_bf16(cc, (const uint32_t*)&A1[kt], wf2[kt][nt], wf2[kt][nt + 2]);
                    mma_bf16(cc, (const uint32_t*)&A2[kt], wf1[kt][nt], wf1[kt][nt + 2]);
                }
            }
        }

        // publish partials: Red[ks][slot][lane] (slot = mt*4 + nt*2 + rr)
#pragma unroll
        for (int mt = 0; mt < 2; mt++)
#pragma unroll
            for (int nt = 0; nt < 2; nt++)
#pragma unroll
                for (int rr = 0; rr < 2; rr++) {
                    int s = mt * 4 + nt * 2 + rr;
                    Red[(size_t)(ks * 8 + s) * 32 + lane] =
                        pack2(acc[mt][nt][rr * 2], acc[mt][nt][rr * 2 + 1]);
                }
        __syncthreads();

        // 16-way reduce + tanh epilogue + frag store (256 threads)
        if (tid < 256) {
            const int l = tid & 31, s = tid >> 5;
            unsigned long long sum = Red[(size_t)s * 32 + l];
#pragma unroll
            for (int q = 1; q < 16; q++)
                sum = add2(sum, Red[(size_t)(q * 8 + s) * 32 + l]);
            float2 f = unpack2(sum);

            const int mtl = s >> 2, nt = (s >> 1) & 1, rr = s & 1;
            const int row = hb * 32 + mtl * 16 + rr * 8 + (l >> 2);
            const int col = n0 + nt * 8 + 2 * (l & 3);
            float* op = states + (size_t)t * (RB * RH) + (size_t)row * RH + col;
            float2 xp = *(float2*)op;
            float v0 = tanhf(xp.x + f.x);
            float v1 = tanhf(xp.y + f.y);
            *(float2*)op = make_float2(v0, v1);

            uint32_t q1 = cvt2bf(v0, v1);
            float e0 = v0 - __uint_as_float(q1 << 16);
            float e1 = v1 - __uint_as_float(q1 & 0xFFFF0000u);
            uint32_t idx = (uint32_t)(((kt_self * 4 + hb * 2 + mtl) * 32 + l) * 4 +
                                      rr + 2 * nt);
            stcg32u(&g_hA[t & 1][0][idx], q1);
            stcg32u(&g_hA[t & 1][1][idx], cvt2bf(e0, e1));
        }
        __syncthreads();

        if (tid == 0 && t < RT - 1) red_release_add(&g_flag[cid][0], 1u);
    }
}

// ---------------------------------------------------------------------------
extern "C" void kernel_launch(void* const* d_in, const int* in_sizes, int n_in,
                              void* d_out, int out_size)
{
    const float* X    = (const float*)d_in[0];
    const float* W_xh = (const float*)d_in[1];
    const float* W_hh = (const float*)d_in[2];
    const float* b_h  = (const float*)d_in[3];
    const float* W_hq = (const float*)d_in[4];
    const float* b_q  = (const float*)d_in[5];

    float* outputs = (float*)d_out;                      // [T*B, O]
    float* states  = outputs + (size_t)RT * RB * RO;     // [T*B, H]

    const int M = RT * RB;  // 32768

    __nv_bfloat16 *pWxh1, *pWxh2, *pWhq1, *pWhq2, *pWhh1, *pWhh2;
    cudaGetSymbolAddress((void**)&pWxh1, g_Wxh1t);
    cudaGetSymbolAddress((void**)&pWxh2, g_Wxh2t);
    cudaGetSymbolAddress((void**)&pWhq1, g_Whq1t);
    cudaGetSymbolAddress((void**)&pWhq2, g_Whq2t);
    cudaGetSymbolAddress((void**)&pWhh1, g_Whh1t);
    cudaGetSymbolAddress((void**)&pWhh2, g_Whh2t);

    cudaFuncSetAttribute(mma_gemm,
                         cudaFuncAttributeMaxDynamicSharedMemorySize, MM_SMEM);
    cudaFuncSetAttribute(rnn_rec_mma,
                         cudaFuncAttributeMaxDynamicSharedMemorySize, REC_SMEM);

    // weight transforms (first resets flag state)
    wsplit<<<dim3(RH / 32, RI / 32), 256>>>(W_xh, pWxh1, pWxh2, RI, RH, 1);
    wsplit<<<dim3(RO / 32, RH / 32), 256>>>(W_hq, pWhq1, pWhq2, RH, RO, 0);
    wsplit<<<dim3(RH / 32, RH / 32), 256>>>(W_hh, pWhh1, pWhh2, RH, RH, 0);

    // Xproj: states <- X @ W_xh + b_h
    mma_gemm<<<dim3(RH / 64, M / 128), 256, MM_SMEM>>>(
        X, pWxh1, pWxh2, b_h, states, M, RH, RI);

    // tensorized recurrence
    rnn_rec_mma<<<128, 512, REC_SMEM>>>(pWhh1, pWhh2, states);

    // outputs <- states @ W_hq + b_q
    mma_gemm<<<dim3(RO / 64, M / 128), 256, MM_SMEM>>>(
        states, pWhq1, pWhq2, b_q, outputs, M, RO, RH);
}

// round 16
// speedup vs baseline: 2.1552x; 1.0223x over previous
#include <cuda_runtime.h>
#include <cuda_bf16.h>
#include <cstdint>

// ---------------------------------------------------------------------------
// RNN: h_t = tanh(X_t @ W_xh + b_h + h_{t-1} @ W_hh) ; y_t = h_t @ W_hq + b_q
// out = [outputs (T*B*O floats) | states (T*B*H floats)]
// T=512 B=64 H=1024 I=512 O=512
//
// R16: recurrence CTA widened to 32 cols x 32-batch-half (64 CTAs) -> h L2
// broadcast halved to 8MB/step. W frags ldmatrix'd from smem per step.
// A-frag h layout, per-producer flags, Red reduce: all proven R15 machinery.
// ---------------------------------------------------------------------------

#define RT 512
#define RB 64
#define RH 1024
#define RI 512
#define RO 512

// per-CTA epoch flags (one 128B line each)
__device__ unsigned g_flag[64][32];
// h in mma A-frag layout: [pingpong][split][(ktile*4 + hb*2 + mt)*32+lane][q]
__device__ __align__(16) uint32_t g_hA[2][2][256 * 32 * 4];
// split+transposed weights: Wt[n][k] bf16
__device__ __align__(16) __nv_bfloat16 g_Wxh1t[RH * RI];
__device__ __align__(16) __nv_bfloat16 g_Wxh2t[RH * RI];
__device__ __align__(16) __nv_bfloat16 g_Whq1t[RO * RH];
__device__ __align__(16) __nv_bfloat16 g_Whq2t[RO * RH];
__device__ __align__(16) __nv_bfloat16 g_Whh1t[RH * RH];
__device__ __align__(16) __nv_bfloat16 g_Whh2t[RH * RH];

// ---- helpers ----
__device__ __forceinline__ unsigned long long pack2(float lo, float hi) {
    unsigned long long r;
    asm("mov.b64 %0, {%1, %2};" : "=l"(r) : "f"(lo), "f"(hi));
    return r;
}
__device__ __forceinline__ float2 unpack2(unsigned long long v) {
    float lo, hi;
    asm("mov.b64 {%0, %1}, %2;" : "=f"(lo), "=f"(hi) : "l"(v));
    return make_float2(lo, hi);
}
__device__ __forceinline__ unsigned long long add2(unsigned long long a,
                                                   unsigned long long b) {
    unsigned long long d;
    asm("add.rn.f32x2 %0, %1, %2;" : "=l"(d) : "l"(a), "l"(b));
    return d;
}
__device__ __forceinline__ void stcg32u(void* p, uint32_t v) {
    asm volatile("st.global.cg.u32 [%0], %1;" :: "l"(p), "r"(v));
}
__device__ __forceinline__ uint4 ldcg128(const void* p) {
    uint4 v;
    asm volatile("ld.global.cg.v4.u32 {%0,%1,%2,%3}, [%4];"
                 : "=r"(v.x), "=r"(v.y), "=r"(v.z), "=r"(v.w) : "l"(p));
    return v;
}
__device__ __forceinline__ void red_release_add(unsigned* p, unsigned v) {
    asm volatile("red.release.gpu.global.add.u32 [%0], %1;" :: "l"(p), "r"(v)
                 : "memory");
}
__device__ __forceinline__ unsigned ld_acquire(const unsigned* p) {
    unsigned v;
    asm volatile("ld.acquire.gpu.global.u32 %0, [%1];" : "=r"(v) : "l"(p)
                 : "memory");
    return v;
}
__device__ __forceinline__ uint32_t smem_u32(const void* p) {
    uint32_t a;
    asm("{ .reg .u64 t; cvta.to.shared.u64 t, %1; cvt.u32.u64 %0, t; }"
        : "=r"(a) : "l"(p));
    return a;
}
__device__ __forceinline__ uint32_t cvt2bf(float lo, float hi) {
    uint32_t r;
    asm("cvt.rn.bf16x2.f32 %0, %1, %2;" : "=r"(r) : "f"(hi), "f"(lo));
    return r;
}
__device__ __forceinline__ void ldm4(uint32_t* r, uint32_t addr) {
    asm volatile(
        "ldmatrix.sync.aligned.m8n8.x4.shared.b16 {%0,%1,%2,%3}, [%4];"
        : "=r"(r[0]), "=r"(r[1]), "=r"(r[2]), "=r"(r[3]) : "r"(addr));
}
__device__ __forceinline__ void mma_bf16(float* c, const uint32_t* a,
                                         uint32_t b0, uint32_t b1) {
    asm volatile(
        "mma.sync.aligned.m16n8k16.row.col.f32.bf16.bf16.f32 "
        "{%0,%1,%2,%3}, {%4,%5,%6,%7}, {%8,%9}, {%0,%1,%2,%3};"
        : "+f"(c[0]), "+f"(c[1]), "+f"(c[2]), "+f"(c[3])
        : "r"(a[0]), "r"(a[1]), "r"(a[2]), "r"(a[3]), "r"(b0), "r"(b1));
}

// ---------------------------------------------------------------------------
// wsplit: W[K,N] fp32 -> Wt1/Wt2[N,K] bf16 (transpose + 2-term split).
// ---------------------------------------------------------------------------
__global__ __launch_bounds__(256) void wsplit(
    const float* __restrict__ W, __nv_bfloat16* __restrict__ Wt1,
    __nv_bfloat16* __restrict__ Wt2, int K, int N, int reset)
{
    __shared__ float tile[32][33];
    const int tx = threadIdx.x & 31, ty = threadIdx.x >> 5;
    const int bx = blockIdx.x, by = blockIdx.y;
    if (reset && bx == 0 && by == 0 && ty == 0) {
#pragma unroll
        for (int c = tx; c < 64; c += 32) g_flag[c][0] = 0u;
    }
    const int n = bx * 32 + tx;
#pragma unroll
    for (int i = 0; i < 4; i++) {
        int k = by * 32 + ty + i * 8;
        tile[ty + i * 8][tx] = W[(size_t)k * N + n];
    }
    __syncthreads();
    const int k2 = by * 32 + tx;
#pragma unroll
    for (int i = 0; i < 4; i++) {
        int n2 = bx * 32 + ty + i * 8;
        float v = tile[tx][ty + i * 8];
        __nv_bfloat16 b1 = __float2bfloat16_rn(v);
        float r = v - __bfloat162float(b1);
        Wt1[(size_t)n2 * K + k2] = b1;
        Wt2[(size_t)n2 * K + k2] = __float2bfloat16_rn(r);
    }
}

// ---------------------------------------------------------------------------
// mma_gemm (unchanged, proven R11): C = A(fp32) @ Wt + bias
// ---------------------------------------------------------------------------
#define AS1 0
#define AS2 18432
#define BS1 36864
#define BS2 46080
#define BIAS_OFF 55296
#define MM_SMEM 55552
#define RSTR 144

__global__ __launch_bounds__(256) void mma_gemm(
    const float* __restrict__ A,
    const __nv_bfloat16* __restrict__ Bt1,
    const __nv_bfloat16* __restrict__ Bt2,
    const float* __restrict__ bias, float* __restrict__ C,
    int M, int N, int K)
{
    extern __shared__ __align__(16) char ts[];
    const uint32_t sb = smem_u32(ts);
    float* sBias = (float*)(ts + BIAS_OFF);

    const int tid = threadIdx.x;
    const int wid = tid >> 5;
    const int lane = tid & 31;
    const int n0 = blockIdx.x * 64;
    const int m0 = blockIdx.y * 128;

    const int mw = (wid & 3) * 32;
    const int nw = (wid >> 2) * 32;
    const int l16 = lane & 15;
    const int lhi = lane >> 4;

    if (tid < 64) sBias[tid] = bias[n0 + tid];

    float acc[2][4][4];
#pragma unroll
    for (int i = 0; i < 2; i++)
#pragma unroll
        for (int j = 0; j < 4; j++)
#pragma unroll
            for (int q = 0; q < 4; q++) acc[i][j][q] = 0.0f;

    const int sr = tid >> 4;
    const int sc = tid & 15;
    const int br = tid >> 3;
    const int bc = tid & 7;

    const int nch = K >> 6;
    for (int c = 0; c < nch; ++c) {
        const int k0 = c << 6;
        if (c > 0) __syncthreads();

#pragma unroll
        for (int it = 0; it < 8; it++) {
            int r = sr + it * 16;
            float4 v = *(const float4*)(A + (size_t)(m0 + r) * K + k0 + sc * 4);
            uint32_t p1a = cvt2bf(v.x, v.y);
            uint32_t p1b = cvt2bf(v.z, v.w);
            float fx = v.x - __uint_as_float(p1a << 16);
            float fy = v.y - __uint_as_float(p1a & 0xFFFF0000u);
            float fz = v.z - __uint_as_float(p1b << 16);
            float fw = v.w - __uint_as_float(p1b & 0xFFFF0000u);
            uint32_t p2a = cvt2bf(fx, fy);
            uint32_t p2b = cvt2bf(fz, fw);
            uint32_t off = (uint32_t)(r * RSTR + sc * 8);
            *(unsigned long long*)(ts + AS1 + off) =
                (unsigned long long)p1a | ((unsigned long long)p1b << 32);
            *(unsigned long long*)(ts + AS2 + off) =
                (unsigned long long)p2a | ((unsigned long long)p2b << 32);
        }
#pragma unroll
        for (int it = 0; it < 2; it++) {
            int r = br + it * 32;
            size_t go = (size_t)(n0 + r) * K + k0 + bc * 8;
            uint4 v1 = *(const uint4*)(Bt1 + go);
            uint4 v2 = *(const uint4*)(Bt2 + go);
            uint32_t off = (uint32_t)(r * RSTR + bc * 16);
            *(uint4*)(ts + BS1 + off) = v1;
            *(uint4*)(ts + BS2 + off) = v2;
        }
        __syncthreads();

#pragma unroll
        for (int ks = 0; ks < 4; ks++) {
            const uint32_t kb = (uint32_t)((ks * 16 + lhi * 8) * 2);

            uint32_t a1[2][4], a2[2][4];
#pragma unroll
            for (int mf = 0; mf < 2; mf++) {
                uint32_t ao = (uint32_t)((mw + mf * 16 + l16) * RSTR) + kb;
                ldm4(a1[mf], sb + AS1 + ao);
                ldm4(a2[mf], sb + AS2 + ao);
            }
            uint32_t b1[2][4], b2[2][4];
#pragma unroll
            for (int np = 0; np < 2; np++) {
                uint32_t bo = (uint32_t)((nw + np * 16 + l16) * RSTR) + kb;
                ldm4(b1[np], sb + BS1 + bo);
                ldm4(b2[np], sb + BS2 + bo);
            }
#pragma unroll
            for (int mf = 0; mf < 2; mf++)
#pragma unroll
                for (int np = 0; np < 2; np++)
#pragma unroll
                    for (int hf = 0; hf < 2; hf++) {
                        float* cc = acc[mf][np * 2 + hf];
                        mma_bf16(cc, a1[mf], b1[np][hf], b1[np][hf + 2]);
                        mma_bf16(cc, a1[mf], b2[np][hf], b2[np][hf + 2]);
                        mma_bf16(cc, a2[mf], b1[np][hf], b1[np][hf + 2]);
                    }
        }
    }
    __syncthreads();

    const int g = lane >> 2;
    const int t = lane & 3;
#pragma unroll
    for (int mf = 0; mf < 2; mf++) {
#pragma unroll
        for (int nf = 0; nf < 4; nf++) {
            const int col = nw + nf * 8 + 2 * t;
            const float bx0 = sBias[col];
            const float bx1 = sBias[col + 1];
            const int row = m0 + mf * 16 + mw + g;
            float* cp = C + (size_t)row * N + n0 + col;
            float2 o0 = make_float2(acc[mf][nf][0] + bx0, acc[mf][nf][1] + bx1);
            float2 o1 = make_float2(acc[mf][nf][2] + bx0, acc[mf][nf][3] + bx1);
            *(float2*)cp = o0;
            *(float2*)(cp + (size_t)8 * N) = o1;
        }
    }
}

// ---------------------------------------------------------------------------
// rnn_rec_mma: tensorized recurrence. 64 CTAs x 512 threads (16 warps).
// CTA cid: cg = cid&31 -> cols n0 = cg*32 (ktiles 2cg, 2cg+1); hb = cid>>5.
// Warp ks: k in [64ks, 64ks+64) = ktiles 4ks..4ks+3 -> producers
// hb*32 + 2ks + {0,1} (lanes 0-1 poll). W frags ldmatrix'd per step.
// Red[ks16][slot16][lane32] u64; slot = mt*8 + nt*2 + rr.
// ---------------------------------------------------------------------------
#define RW1 0
#define RW2 66048
#define RREDB 132096
#define REC_SMEM 197632

__global__ __launch_bounds__(512) void rnn_rec_mma(
    const __nv_bfloat16* __restrict__ Whh1,
    const __nv_bfloat16* __restrict__ Whh2,
    float* __restrict__ states)
{
    extern __shared__ __align__(16) char rs[];
    const uint32_t sb = smem_u32(rs);
    unsigned long long* Red = (unsigned long long*)(rs + RREDB);

    const int tid = threadIdx.x;
    const int ks = tid >> 5;
    const int lane = tid & 31;
    const int cid = blockIdx.x;
    const int hb = cid >> 5;
    const int cg = cid & 31;
    const int n0 = cg * 32;

    unsigned* myflag = &g_flag[hb * 32 + 2 * ks + (lane & 1)][0];

    // one-time: W_hh slice [32 n][1024 k] x2 splits into smem (stride 2064)
    for (int idx = tid; idx < 32 * 128; idx += 512) {
        int r = idx >> 7, c = idx & 127;
        *(uint4*)(rs + RW1 + r * 2064 + c * 16) =
            *(const uint4*)(Whh1 + (size_t)(n0 + r) * RH + c * 8);
        *(uint4*)(rs + RW2 + r * 2064 + c * 16) =
            *(const uint4*)(Whh2 + (size_t)(n0 + r) * RH + c * 8);
    }
    __syncthreads();

    // t = 0: h_0 = tanh(xp); slot s = tid>>5, lane l = tid&31
    {
        const int l = lane, s = ks;
        const int mt = s >> 3, nt = (s & 7) >> 1, rr = s & 1;
        const int row = hb * 32 + mt * 16 + rr * 8 + (l >> 2);
        const int col = n0 + nt * 8 + 2 * (l & 3);
        float* op = states + (size_t)row * RH + col;
        float2 xp = *(float2*)op;
        float v0 = tanhf(xp.x), v1 = tanhf(xp.y);
        *(float2*)op = make_float2(v0, v1);
        uint32_t q1 = cvt2bf(v0, v1);
        float e0 = v0 - __uint_as_float(q1 << 16);
        float e1 = v1 - __uint_as_float(q1 & 0xFFFF0000u);
        const int kt = cg * 2 + (nt >> 1);
        uint32_t idx = (uint32_t)(((kt * 4 + hb * 2 + mt) * 32 + l) * 4 +
                                  rr + 2 * (nt & 1));
        stcg32u(&g_hA[0][0][idx], q1);
        stcg32u(&g_hA[0][1][idx], cvt2bf(e0, e1));
    }
    __syncthreads();
    if (tid == 0) red_release_add(&g_flag[cid][0], 1u);

    for (int t = 1; t < RT; ++t) {
        const int pp_r = (t - 1) & 1;

        if (lane < 2) {
            while (ld_acquire(myflag) < (unsigned)t) {}
        }
        __syncwarp();

        float acc[2][4][4];
#pragma unroll
        for (int mt = 0; mt < 2; mt++)
#pragma unroll
            for (int nt = 0; nt < 4; nt++)
#pragma unroll
                for (int q = 0; q < 4; q++) acc[mt][nt][q] = 0.0f;

#pragma unroll
        for (int kt = 0; kt < 4; kt++) {
            // A frags: 2 mtiles x 2 splits (LDG.128 each, coalesced)
            uint4 A1[2], A2[2];
#pragma unroll
            for (int mt = 0; mt < 2; mt++) {
                uint32_t base = (uint32_t)(
                    (((ks * 4 + kt) * 4 + hb * 2 + mt) * 32 + lane) * 4);
                A1[mt] = ldcg128(&g_hA[pp_r][0][base]);
                A2[mt] = ldcg128(&g_hA[pp_r][1][base]);
            }
            // W frags: 2 n16-halves x 2 splits via ldmatrix
            uint32_t w1[2][4], w2[2][4];
#pragma unroll
            for (int p = 0; p < 2; p++) {
                uint32_t bo = (uint32_t)(
                    (p * 16 + (lane & 15)) * 2064 +
                    ((ks * 4 + kt) * 16 + (lane >> 4) * 8) * 2);
                ldm4(w1[p], sb + RW1 + bo);
                ldm4(w2[p], sb + RW2 + bo);
            }
#pragma unroll
            for (int mt = 0; mt < 2; mt++)
#pragma unroll
                for (int p = 0; p < 2; p++)
#pragma unroll
                    for (int ntl = 0; ntl < 2; ntl++) {
                        float* cc = acc[mt][p * 2 + ntl];
                        mma_bf16(cc, (const uint32_t*)&A1[mt],
                                 w1[p][ntl], w1[p][ntl + 2]);
                        mma_bf16(cc, (const uint32_t*)&A1[mt],
                                 w2[p][ntl], w2[p][ntl + 2]);
                        mma_bf16(cc, (const uint32_t*)&A2[mt],
                                 w1[p][ntl], w1[p][ntl + 2]);
                    }
        }

        // publish partials: Red[ks][slot][lane], slot = mt*8 + nt*2 + rr
#pragma unroll
        for (int mt = 0; mt < 2; mt++)
#pragma unroll
            for (int nt = 0; nt < 4; nt++)
#pragma unroll
                for (int rr = 0; rr < 2; rr++) {
                    int s = mt * 8 + nt * 2 + rr;
                    Red[(size_t)(ks * 16 + s) * 32 + lane] =
                        pack2(acc[mt][nt][rr * 2], acc[mt][nt][rr * 2 + 1]);
                }
        __syncthreads();

        // 16-way reduce + tanh epilogue + frag store (all 512 threads)
        {
            const int l = lane, s = ks;
            unsigned long long sum = Red[(size_t)s * 32 + l];
#pragma unroll
            for (int q = 1; q < 16; q++)
                sum = add2(sum, Red[(size_t)(q * 16 + s) * 32 + l]);
            float2 f = unpack2(sum);

            const int mt = s >> 3, nt = (s & 7) >> 1, rr = s & 1;
            const int row = hb * 32 + mt * 16 + rr * 8 + (l >> 2);
            const int col = n0 + nt * 8 + 2 * (l & 3);
            float* op = states + (size_t)t * (RB * RH) + (size_t)row * RH + col;
            float2 xp = *(float2*)op;
            float v0 = tanhf(xp.x + f.x);
            float v1 = tanhf(xp.y + f.y);
            *(float2*)op = make_float2(v0, v1);

            uint32_t q1 = cvt2bf(v0, v1);
            float e0 = v0 - __uint_as_float(q1 << 16);
            float e1 = v1 - __uint_as_float(q1 & 0xFFFF0000u);
            const int kt = cg * 2 + (nt >> 1);
            uint32_t idx = (uint32_t)(((kt * 4 + hb * 2 + mt) * 32 + l) * 4 +
                                      rr + 2 * (nt & 1));
            stcg32u(&g_hA[t & 1][0][idx], q1);
            stcg32u(&g_hA[t & 1][1][idx], cvt2bf(e0, e1));
        }
        __syncthreads();

        if (tid == 0 && t < RT - 1) red_release_add(&g_flag[cid][0], 1u);
    }
}

// ---------------------------------------------------------------------------
extern "C" void kernel_launch(void* const* d_in, const int* in_sizes, int n_in,
                              void* d_out, int out_size)
{
    const float* X    = (const float*)d_in[0];
    const float* W_xh = (const float*)d_in[1];
    const float* W_hh = (const float*)d_in[2];
    const float* b_h  = (const float*)d_in[3];
    const float* W_hq = (const float*)d_in[4];
    const float* b_q  = (const float*)d_in[5];

    float* outputs = (float*)d_out;                      // [T*B, O]
    float* states  = outputs + (size_t)RT * RB * RO;     // [T*B, H]

    const int M = RT * RB;  // 32768

    __nv_bfloat16 *pWxh1, *pWxh2, *pWhq1, *pWhq2, *pWhh1, *pWhh2;
    cudaGetSymbolAddress((void**)&pWxh1, g_Wxh1t);
    cudaGetSymbolAddress((void**)&pWxh2, g_Wxh2t);
    cudaGetSymbolAddress((void**)&pWhq1, g_Whq1t);
    cudaGetSymbolAddress((void**)&pWhq2, g_Whq2t);
    cudaGetSymbolAddress((void**)&pWhh1, g_Whh1t);
    cudaGetSymbolAddress((void**)&pWhh2, g_Whh2t);

    cudaFuncSetAttribute(mma_gemm,
                         cudaFuncAttributeMaxDynamicSharedMemorySize, MM_SMEM);
    cudaFuncSetAttribute(rnn_rec_mma,
                         cudaFuncAttributeMaxDynamicSharedMemorySize, REC_SMEM);

    // weight transforms (first resets flag state)
    wsplit<<<dim3(RH / 32, RI / 32), 256>>>(W_xh, pWxh1, pWxh2, RI, RH, 1);
    wsplit<<<dim3(RO / 32, RH / 32), 256>>>(W_hq, pWhq1, pWhq2, RH, RO, 0);
    wsplit<<<dim3(RH / 32, RH / 32), 256>>>(W_hh, pWhh1, pWhh2, RH, RH, 0);

    // Xproj: states <- X @ W_xh + b_h
    mma_gemm<<<dim3(RH / 64, M / 128), 256, MM_SMEM>>>(
        X, pWxh1, pWxh2, b_h, states, M, RH, RI);

    // tensorized recurrence
    rnn_rec_mma<<<64, 512, REC_SMEM>>>(pWhh1, pWhh2, states);

    // outputs <- states @ W_hq + b_q
    mma_gemm<<<dim3(RO / 64, M / 128), 256, MM_SMEM>>>(
        states, pWhq1, pWhq2, b_q, outputs, M, RO, RH);
}